// round 12
// baseline (speedup 1.0000x reference)
#include <cuda_runtime.h>
#include <cuda_bf16.h>

#define NN     50000
#define NPAD   50048        // 782 * 64
#define SS     2048
#define KK     64
#define HH     128
#define EE     524288
#define LL     5
#define MROWS  (SS*KK)      // 131072
#define PL     34816        // full smem plane: 128 rows x 272B
#define APL64  17408        // 64-row plane
#define NSM    148
#define NT     512          // threads per persistent GEMM CTA (16 warps)

typedef unsigned short u16;
typedef unsigned int   u32;

// ---------------- scratch (device globals; no allocations) ----------------
__device__ u16 g_Mb[2*16384];          // folded init weight planes [hi][lo], [n][k]
__device__ u16 g_w1b[LL*2*16384];
__device__ u16 g_w2b[LL*2*16384];
__device__ u16 g_mp2b[LL*4*16384];     // [l][half][plane][n][k]
__device__ float g_vlogp[HH];
__device__ float g_bias0[HH];
__device__ float g_root[2*HH];
__device__ u16 g_xph[NPAD*HH],  g_xpl[NPAD*HH];    // packed x (tail zero)
__device__ u16 g_zph[MROWS*HH], g_zpl[MROWS*HH];
__device__ u16 g_z2h[MROWS*HH], g_z2l[MROWS*HH];
__device__ u16 g_xah[NPAD*HH],  g_xal[NPAD*HH];    // packed xagg*inv (tail zero)
__device__ float g_y0[NPAD*HH];        // x @ M
__device__ float g_y2[NPAD*HH];        // (xagg*inv) @ Wmp2_half1
__device__ float g_u[MROWS*HH];
__device__ float g_xagg[NN*HH];
__device__ float g_inv[NN];
__device__ int   g_cnt[NN];
__device__ float g_stats[2*HH];

// ---------------- helpers ----------------
__device__ __forceinline__ void splitf(float v, u16& h, u16& l) {
    __nv_bfloat16 hb = __float2bfloat16_rn(v);
    __nv_bfloat16 lb = __float2bfloat16_rn(v - __bfloat162float(hb));
    h = __bfloat16_as_ushort(hb);
    l = __bfloat16_as_ushort(lb);
}
__device__ __forceinline__ void pack2(float v0, float v1, u32& hi, u32& lo) {
    u16 h0, l0, h1, l1;
    splitf(v0, h0, l0); splitf(v1, h1, l1);
    hi = (u32)h0 | ((u32)h1 << 16);
    lo = (u32)l0 | ((u32)l1 << 16);
}
__device__ __forceinline__ u32 smem_u32(const void* p) {
    u32 a;
    asm("{ .reg .u64 t; cvta.to.shared.u64 t, %1; cvt.u32.u64 %0, t; }" : "=r"(a) : "l"(p));
    return a;
}

#define CP16(dst, src) \
    asm volatile("cp.async.cg.shared.global [%0], [%1], 16;" :: "r"(dst), "l"(src) : "memory")
#define CPCOMMIT() asm volatile("cp.async.commit_group;" ::: "memory")
#define CPWAIT(n)  asm volatile("cp.async.wait_group %0;" :: "n"(n) : "memory")

#define LDSM4(R0,R1,R2,R3,ADDR) \
    asm volatile("ldmatrix.sync.aligned.m8n8.x4.shared.b16 {%0,%1,%2,%3}, [%4];" \
        : "=r"(R0),"=r"(R1),"=r"(R2),"=r"(R3) : "r"(ADDR))

#define MMA_BF16(C, A0,A1,A2,A3, B0,B1) \
    asm volatile("mma.sync.aligned.m16n8k16.row.col.f32.bf16.bf16.f32 " \
        "{%0,%1,%2,%3},{%4,%5,%6,%7},{%8,%9},{%0,%1,%2,%3};" \
        : "+f"(C[0]),"+f"(C[1]),"+f"(C[2]),"+f"(C[3]) \
        : "r"(A0),"r"(A1),"r"(A2),"r"(A3),"r"(B0),"r"(B1))

// ---- 64-row 3-term core, 16-warp layout (warp tile 16m x 32n) ----
__device__ __forceinline__ void gemm64w16(u32 aB, u32 bB,
                                          u32 ar, const u32* br, float c[4][4])
{
    #pragma unroll
    for (int ks = 0; ks < 8; ks++) {
        const u32 ko = ks*32;
        unsigned ah[4], al[4], bh[2][4], bl[2][4];
        LDSM4(ah[0],ah[1],ah[2],ah[3], aB + ar + ko);
        LDSM4(al[0],al[1],al[2],al[3], aB + APL64 + ar + ko);
        LDSM4(bh[0][0],bh[0][1],bh[0][2],bh[0][3], bB + br[0] + ko);
        LDSM4(bh[1][0],bh[1][1],bh[1][2],bh[1][3], bB + br[1] + ko);
        #pragma unroll
        for (int g = 0; g < 2; g++) {
            MMA_BF16(c[2*g+0], ah[0],ah[1],ah[2],ah[3], bh[g][0],bh[g][2]);
            MMA_BF16(c[2*g+1], ah[0],ah[1],ah[2],ah[3], bh[g][1],bh[g][3]);
        }
        LDSM4(bl[0][0],bl[0][1],bl[0][2],bl[0][3], bB + PL + br[0] + ko);
        LDSM4(bl[1][0],bl[1][1],bl[1][2],bl[1][3], bB + PL + br[1] + ko);
        #pragma unroll
        for (int g = 0; g < 2; g++) {
            MMA_BF16(c[2*g+0], al[0],al[1],al[2],al[3], bh[g][0],bh[g][2]);
            MMA_BF16(c[2*g+1], al[0],al[1],al[2],al[3], bh[g][1],bh[g][3]);
        }
        #pragma unroll
        for (int g = 0; g < 2; g++) {
            MMA_BF16(c[2*g+0], ah[0],ah[1],ah[2],ah[3], bl[g][0],bl[g][2]);
            MMA_BF16(c[2*g+1], ah[0],ah[1],ah[2],ah[3], bl[g][1],bl[g][3]);
        }
    }
}

#define ZERO_C4(c) { _Pragma("unroll") for (int j=0;j<4;j++) \
    _Pragma("unroll") for (int q=0;q<4;q++) (c)[j][q]=0.f; }

// ---- smem loaders (512 threads; caller commits) ----
__device__ __forceinline__ void loadW(u32 dst, const u16* blob, int tid) {
    #pragma unroll
    for (int it = 0; it < 8; it++) {
        int ch = tid + it*NT;
        int pl = ch >> 11, rem = ch & 2047, r = rem >> 4, q = rem & 15;
        CP16(dst + pl*PL + r*272 + q*16, blob + (size_t)pl*16384 + r*128 + q*8);
    }
}
__device__ __forceinline__ void loadA64(u32 dst, const u16* Ah, const u16* Al,
                                        int rowbase, const int* idx, int tid) {
    #pragma unroll
    for (int it = 0; it < 4; it++) {
        int ch = tid + it*NT;
        int pl = ch >> 10, rem = ch & 1023, r = rem >> 4, q = rem & 15;
        int row = idx ? idx[rowbase + r] : (rowbase + r);
        CP16(dst + pl*APL64 + r*272 + q*16, (pl ? Al : Ah) + (size_t)row*HH + q*8);
    }
}
__device__ __forceinline__ void frag_b(int lane, int wn, u32* br) {
    #pragma unroll
    for (int g = 0; g < 2; g++) {
        int row = wn*32 + g*16 + ((lane>>3)&1)*8 + (lane&7);
        br[g] = row*272 + (lane>>4)*16;
    }
}

// ---------------- packing kernels ----------------
__global__ void pack_x_kernel(const float* __restrict__ x) {
    int idx = blockIdx.x*256 + threadIdx.x;    // covers NN*HH exactly
    u16 h, l; splitf(x[idx], h, l);
    g_xph[idx] = h; g_xpl[idx] = l;
}
__global__ void fold_M_kernel(const float* __restrict__ npw, const float* __restrict__ ipw) {
    int k = blockIdx.x, n = threadIdx.x;
    float s = 0.f;
    for (int c = 0; c < HH; c++) s += npw[k*HH + c] * ipw[c*HH + n];
    u16 h, l; splitf(s, h, l);
    g_Mb[n*128 + k] = h; g_Mb[16384 + n*128 + k] = l;
}
__global__ void fold_vec_kernel(const float* __restrict__ lpw, const float* __restrict__ npb,
                                const float* __restrict__ lpb, const float* __restrict__ remb,
                                const float* __restrict__ ipw, const float* __restrict__ ipb) {
    int j = threadIdx.x;
    float v = 0.f, b = ipb[j], r0 = 0.f, r1 = 0.f;
    for (int k = 0; k < HH; k++) {
        float wa = ipw[k*HH + j];
        float wb = ipw[(HH + k)*HH + j];
        float wc = ipw[(2*HH + k)*HH + j];
        v  += lpw[k] * wb;
        b  += npb[k] * wa + lpb[k] * wb;
        r0 += remb[k] * wc;
        r1 += remb[HH + k] * wc;
    }
    g_vlogp[j] = v; g_bias0[j] = b; g_root[j] = r0; g_root[HH + j] = r1;
}
__global__ void pack_w128(const float* __restrict__ W, u16* __restrict__ out) {
    int l = blockIdx.y;
    int idx = blockIdx.x*256 + threadIdx.x;
    int k = idx >> 7, n = idx & 127;
    u16 h, lo; splitf(W[(size_t)l*16384 + idx], h, lo);
    out[(size_t)l*32768 + n*128 + k] = h;
    out[(size_t)l*32768 + 16384 + n*128 + k] = lo;
}
__global__ void pack_w256(const float* __restrict__ W, u16* __restrict__ out) {
    int l = blockIdx.y;
    int idx = blockIdx.x*256 + threadIdx.x;
    int kg = idx >> 7, n = idx & 127;
    int half = kg >> 7, kl = kg & 127;
    u16 h, lo; splitf(W[(size_t)l*32768 + idx], h, lo);
    out[(size_t)l*65536 + half*32768 + n*128 + kl] = h;
    out[(size_t)l*65536 + half*32768 + 16384 + n*128 + kl] = lo;
}

// ---------------- counts ----------------
__global__ void zero_cnt_kernel() {
    int i = blockIdx.x*blockDim.x + threadIdx.x;
    if (i < NN) g_cnt[i] = 0;
}
__global__ void count_kernel(const int* __restrict__ nodes) {
    int i = blockIdx.x*blockDim.x + threadIdx.x;
    if (i < MROWS) atomicAdd(&g_cnt[nodes[i]], 1);
}
__global__ void inv_kernel() {
    int i = blockIdx.x*blockDim.x + threadIdx.x;
    if (i < NN) g_inv[i] = 1.f / (float)max(g_cnt[i], 1);
}
__global__ void zero_xagg_kernel() {
    int i = blockIdx.x*blockDim.x + threadIdx.x;
    g_xagg[i] = 0.f;
    if (i < 2*HH) g_stats[i] = 0.f;
}
__global__ void pack_xagg_kernel() {
    int idx = blockIdx.x*256 + threadIdx.x;    // covers NN*HH exactly
    int row = idx >> 7;
    float v = g_xagg[idx] * g_inv[row];
    u16 h, l; splitf(v, h, l);
    g_xah[idx] = h; g_xal[idx] = l;
    g_xagg[idx] = 0.f;
    if (blockIdx.x == 0 && threadIdx.x < 2*HH) g_stats[threadIdx.x] = 0.f;
}

// ---------------- persistent plain GEMM over NPAD rows: out = A @ W (fp32) ----------------
__global__ void __launch_bounds__(NT, 1)
ygemm_pers(const u16* __restrict__ Ah, const u16* __restrict__ Al,
           const u16* __restrict__ blob, float* __restrict__ out)
{
    extern __shared__ __align__(16) char sm[];
    const u32 sb = smem_u32(sm);          // W planes [0,2PL); A slots 2PL + s*PL
    const int tid = threadIdx.x, lane = tid & 31, warp = tid >> 5;
    const int wm = warp & 3, wn = warp >> 2;

    loadW(sb, blob, tid);
    loadA64(sb + 2*PL, Ah, Al, blockIdx.x * 64, nullptr, tid);
    CPCOMMIT();

    const u32 ar = (wm*16 + (lane & 15))*272 + (lane>>4)*16;
    u32 br[2]; frag_b(lane, wn, br);
    const int gid = lane >> 2, tig = lane & 3;

    int j = 0;
    for (int t = blockIdx.x; t < NPAD/64; t += NSM, j++) {
        int tn = t + NSM;
        if (tn < NPAD/64) {
            loadA64(sb + 2*PL + ((j+1)&1)*PL, Ah, Al, tn*64, nullptr, tid);
            CPCOMMIT();
            CPWAIT(1);
        } else {
            CPWAIT(0);
        }
        __syncthreads();

        float c[4][4]; ZERO_C4(c);
        gemm64w16(sb + 2*PL + (j&1)*PL, sb, ar, br, c);

        int brow = t * 64;
        #pragma unroll
        for (int half = 0; half < 2; half++) {
            int gr = brow + wm*16 + half*8 + gid;
            #pragma unroll
            for (int nf = 0; nf < 4; nf++) {
                int n0 = wn*32 + nf*8 + tig*2;
                float2 o;
                o.x = c[nf][half*2+0];
                o.y = c[nf][half*2+1];
                *(float2*)(out + (size_t)gr*HH + n0) = o;
            }
        }
        __syncthreads();
    }
}

// ---------------- persistent fused layer kernel (64-row tiles, 16 warps) ----------------
__global__ void __launch_bounds__(NT, 1)
layer12_kernel(const u16* __restrict__ w1b, const u16* __restrict__ w2b,
               const float* __restrict__ b1, const float* __restrict__ b2,
               const int* __restrict__ aidx)
{
    extern __shared__ __align__(16) char sm[];
    const u32 sb = smem_u32(sm);          // W1 [0,2PL); W2 [2PL,4PL); A slots 4PL + s*PL
    const int tid = threadIdx.x, lane = tid & 31, warp = tid >> 5;
    const int wm = warp & 3, wn = warp >> 2;

    loadW(sb, w1b, tid);
    loadW(sb + 2*PL, w2b, tid);
    loadA64(sb + 4*PL, g_zph, g_zpl, blockIdx.x * 64, nullptr, tid);
    CPCOMMIT();

    const u32 ar = (wm*16 + (lane & 15))*272 + (lane>>4)*16;
    u32 br[2]; frag_b(lane, wn, br);
    const int gid = lane >> 2, tig = lane & 3;

    int j = 0;
    for (int t = blockIdx.x; t < MROWS/64; t += NSM, j++) {
        int tn = t + NSM;
        if (tn < MROWS/64) {
            loadA64(sb + 4*PL + ((j+1)&1)*PL, g_zph, g_zpl, tn*64, nullptr, tid);
            CPCOMMIT();
            CPWAIT(1);
        } else {
            CPWAIT(0);
        }
        __syncthreads();

        const u32 aslot = sb + 4*PL + (j&1)*PL;
        float c[4][4]; ZERO_C4(c);
        gemm64w16(aslot, sb, ar, br, c);    // z @ W1
        __syncthreads();                     // all z reads done

        char* aptr = sm + (4*PL + (j&1)*PL);
        #pragma unroll
        for (int half = 0; half < 2; half++) {
            int m = wm*16 + half*8 + gid;
            #pragma unroll
            for (int nf = 0; nf < 4; nf++) {
                int n0 = wn*32 + nf*8 + tig*2;
                float v0 = fmaxf(c[nf][half*2+0] + b1[n0],   0.f);
                float v1 = fmaxf(c[nf][half*2+1] + b1[n0+1], 0.f);
                u32 hi, lo; pack2(v0, v1, hi, lo);
                u32 off = m*272 + n0*2;
                *(u32*)(aptr + off)         = hi;
                *(u32*)(aptr + APL64 + off) = lo;
            }
        }
        __syncthreads();

        ZERO_C4(c);
        gemm64w16(aslot, sb + 2*PL, ar, br, c);   // t @ W2

        int brow = t * 64;
        #pragma unroll
        for (int half = 0; half < 2; half++) {
            int gr = brow + wm*16 + half*8 + gid;
            int nd = aidx[gr];
            #pragma unroll
            for (int nf = 0; nf < 4; nf++) {
                int n0 = wn*32 + nf*8 + tig*2;
                float v0 = c[nf][half*2+0] + b2[n0];
                float v1 = c[nf][half*2+1] + b2[n0+1];
                u32 hi, lo; pack2(v0, v1, hi, lo);
                *(u32*)(g_z2h + (size_t)gr*HH + n0) = hi;
                *(u32*)(g_z2l + (size_t)gr*HH + n0) = lo;
                atomicAdd(&g_xagg[(size_t)nd*HH + n0],     v0);
                atomicAdd(&g_xagg[(size_t)nd*HH + n0 + 1], v1);
            }
        }
        __syncthreads();
    }
}

// ---------------- persistent mp2 kernel: u = relu(z2@Wh0 + y2[nd] + b) + bn stats ----------------
__global__ void __launch_bounds__(NT, 1)
mp2_kernel(const u16* __restrict__ blob, const float* __restrict__ bias,
           const int* __restrict__ aidx, float* __restrict__ uout)
{
    extern __shared__ __align__(16) char sm[];
    const u32 sb = smem_u32(sm);          // Wh0 [0,2PL); A slots 2PL + s*PL
    const int tid = threadIdx.x, lane = tid & 31, warp = tid >> 5;
    const int wm = warp & 3, wn = warp >> 2;

    loadW(sb, blob, tid);
    loadA64(sb + 2*PL, g_z2h, g_z2l, blockIdx.x * 64, nullptr, tid);
    CPCOMMIT();

    const u32 ar = (wm*16 + (lane & 15))*272 + (lane>>4)*16;
    u32 br[2]; frag_b(lane, wn, br);
    const int gid = lane >> 2, tig = lane & 3;

    float s0[4], s1[4], q0[4], q1[4];
    #pragma unroll
    for (int nf = 0; nf < 4; nf++) { s0[nf]=0.f; s1[nf]=0.f; q0[nf]=0.f; q1[nf]=0.f; }

    int j = 0;
    for (int t = blockIdx.x; t < MROWS/64; t += NSM, j++) {
        int tn = t + NSM;
        if (tn < MROWS/64) {
            loadA64(sb + 2*PL + ((j+1)&1)*PL, g_z2h, g_z2l, tn*64, nullptr, tid);
            CPCOMMIT();
            CPWAIT(1);
        } else {
            CPWAIT(0);
        }
        __syncthreads();

        float c[4][4]; ZERO_C4(c);
        gemm64w16(sb + 2*PL + (j&1)*PL, sb, ar, br, c);   // z2 @ Wh0

        int brow = t * 64;
        #pragma unroll
        for (int half = 0; half < 2; half++) {
            int gr = brow + wm*16 + half*8 + gid;
            int nd = aidx[gr];
            const float* y2r = g_y2 + (size_t)nd*HH;
            #pragma unroll
            for (int nf = 0; nf < 4; nf++) {
                int n0 = wn*32 + nf*8 + tig*2;
                float2 yv = *(const float2*)(y2r + n0);
                float v0 = fmaxf(c[nf][half*2+0] + yv.x + bias[n0],   0.f);
                float v1 = fmaxf(c[nf][half*2+1] + yv.y + bias[n0+1], 0.f);
                float2 o; o.x = v0; o.y = v1;
                *(float2*)(uout + (size_t)gr*HH + n0) = o;
                s0[nf] += v0; s1[nf] += v1;
                q0[nf] += v0*v0; q1[nf] += v1*v1;
            }
        }
        __syncthreads();
    }

    #pragma unroll
    for (int nf = 0; nf < 4; nf++) {
        #pragma unroll
        for (int off = 4; off < 32; off <<= 1) {
            s0[nf] += __shfl_xor_sync(0xFFFFFFFFu, s0[nf], off);
            s1[nf] += __shfl_xor_sync(0xFFFFFFFFu, s1[nf], off);
            q0[nf] += __shfl_xor_sync(0xFFFFFFFFu, q0[nf], off);
            q1[nf] += __shfl_xor_sync(0xFFFFFFFFu, q1[nf], off);
        }
    }
    if (gid == 0) {
        #pragma unroll
        for (int nf = 0; nf < 4; nf++) {
            int n0 = wn*32 + nf*8 + tig*2;
            atomicAdd(&g_stats[n0],      s0[nf]);
            atomicAdd(&g_stats[n0+1],    s1[nf]);
            atomicAdd(&g_stats[HH+n0],   q0[nf]);
            atomicAdd(&g_stats[HH+n0+1], q1[nf]);
        }
    }
}

// ---------------- agg ----------------
// MODE 0: init: h = y0[nodes] + lp*v + root + bias0; writes H; acc=(1+eps)*h
// MODE 1: BN fuse: h = bn(u) + H; writes H; acc=(1+eps)*h
template<int MODE>
__global__ void __launch_bounds__(128)
agg_kernel(const float* __restrict__ u, float* __restrict__ H,
           u16* __restrict__ zph, u16* __restrict__ zpl,
           const int* __restrict__ esrc, const int* __restrict__ edst,
           const int* __restrict__ eptr, const float* __restrict__ geps,
           const float* __restrict__ gamma, const float* __restrict__ beta,
           const int* __restrict__ nodes, const float* __restrict__ logp,
           const int* __restrict__ rootl, int l)
{
    extern __shared__ float fsm[];
    float* hsm = fsm;
    float* acc = fsm + KK*HH;
    __shared__ int se[256], de[256];
    const int s = blockIdx.x;
    const int tid = threadIdx.x;
    const float eps1 = 1.f + geps[l];
    const size_t base = (size_t)s * KK;

    float g = 0.f, bt = 0.f, mu = 0.f, cb = 0.f;
    int rloc = -1;
    if (MODE == 1) {
        const float invM = 1.f / (float)MROWS;
        mu = g_stats[tid] * invM;
        float var = g_stats[HH + tid] * invM - mu*mu;
        g = gamma[tid] * rsqrtf(var + 1e-5f);
        bt = beta[tid];
    } else {
        float lp = logp[s];
        rloc = rootl[s];
        cb = g_bias0[tid] + lp * g_vlogp[tid];
    }

    #pragma unroll 4
    for (int r = 0; r < KK; r++) {
        float hv;
        if (MODE == 1) {
            float uv = u[(base + r)*HH + tid];
            hv = (uv - mu) * g + bt + H[(base + r)*HH + tid];
        } else {
            int nd = nodes[base + r];
            hv = g_y0[(size_t)nd*HH + tid] + cb + g_root[(r == rloc ? HH : 0) + tid];
        }
        H[(base + r)*HH + tid] = hv;
        hsm[r*HH + tid] = hv;
        acc[r*HH + tid] = eps1 * hv;
    }
    __syncthreads();

    const int e0 = eptr[s], e1 = eptr[s+1];
    for (int eb = e0; eb < e1; eb += 256) {
        int ne = min(256, e1 - eb);
        for (int i = tid; i < ne; i += 128) {
            se[i] = esrc[eb + i];
            de[i] = edst[eb + i];
        }
        __syncthreads();
        for (int i = 0; i < ne; i++)
            acc[de[i]*HH + tid] += hsm[se[i]*HH + tid];
        __syncthreads();
    }

    #pragma unroll 4
    for (int r = 0; r < KK; r++) {
        u16 h, lo; splitf(acc[r*HH + tid], h, lo);
        zph[(base + r)*HH + tid] = h;
        zpl[(base + r)*HH + tid] = lo;
    }
}

// ---------------- final batchnorm apply ----------------
__global__ void bn_apply_kernel(const float* __restrict__ u, float* __restrict__ h,
                                const float* __restrict__ gamma, const float* __restrict__ beta) {
    int idx = blockIdx.x*blockDim.x + threadIdx.x;
    int c = idx & 127;
    const float invM = 1.f / (float)MROWS;
    float mu  = g_stats[c] * invM;
    float var = g_stats[HH + c] * invM - mu*mu;
    float g = gamma[c] * rsqrtf(var + 1e-5f);
    h[idx] = (u[idx] - mu) * g + beta[c] + h[idx];
}

// ---------------- launch ----------------
extern "C" void kernel_launch(void* const* d_in, const int* in_sizes, int n_in,
                              void* d_out, int out_size) {
    const float* x    = (const float*)d_in[0];
    const float* logp = (const float*)d_in[1];
    const float* npw  = (const float*)d_in[2];
    const float* npb  = (const float*)d_in[3];
    const float* lpw  = (const float*)d_in[4];
    const float* lpb  = (const float*)d_in[5];
    const float* remb = (const float*)d_in[6];
    const float* ipw  = (const float*)d_in[7];
    const float* ipb  = (const float*)d_in[8];
    const float* geps = (const float*)d_in[9];
    const float* w1   = (const float*)d_in[10];
    const float* b1   = (const float*)d_in[11];
    const float* w2   = (const float*)d_in[12];
    const float* b2   = (const float*)d_in[13];
    const float* mp2w = (const float*)d_in[14];
    const float* mp2b = (const float*)d_in[15];
    const float* bng  = (const float*)d_in[16];
    const float* bnb  = (const float*)d_in[17];
    const int* nodes  = (const int*)d_in[18];
    const int* rootl  = (const int*)d_in[19];
    const int* eidx   = (const int*)d_in[20];
    const int* eptr   = (const int*)d_in[21];
    float* hout = (float*)d_out;

    float *p_u, *p_y0, *p_y2;
    u16 *p_zph, *p_zpl, *p_w1b, *p_w2b, *p_mp2b, *p_xph, *p_xpl, *p_xah, *p_xal, *p_Mb;
    cudaGetSymbolAddress((void**)&p_u, g_u);
    cudaGetSymbolAddress((void**)&p_y0, g_y0);
    cudaGetSymbolAddress((void**)&p_y2, g_y2);
    cudaGetSymbolAddress((void**)&p_zph, g_zph);
    cudaGetSymbolAddress((void**)&p_zpl, g_zpl);
    cudaGetSymbolAddress((void**)&p_w1b, g_w1b);
    cudaGetSymbolAddress((void**)&p_w2b, g_w2b);
    cudaGetSymbolAddress((void**)&p_mp2b, g_mp2b);
    cudaGetSymbolAddress((void**)&p_xph, g_xph);
    cudaGetSymbolAddress((void**)&p_xpl, g_xpl);
    cudaGetSymbolAddress((void**)&p_xah, g_xah);
    cudaGetSymbolAddress((void**)&p_xal, g_xal);
    cudaGetSymbolAddress((void**)&p_Mb, g_Mb);

    const int SM_Y    = 4*PL;             // 139264
    const int SM_L12  = 6*PL;             // 208896
    const int SM_MP2  = 4*PL;             // 139264
    const int SMA = 2*KK*HH*4;            // 65536
    cudaFuncSetAttribute(ygemm_pers,     cudaFuncAttributeMaxDynamicSharedMemorySize, SM_Y);
    cudaFuncSetAttribute(layer12_kernel, cudaFuncAttributeMaxDynamicSharedMemorySize, SM_L12);
    cudaFuncSetAttribute(mp2_kernel,     cudaFuncAttributeMaxDynamicSharedMemorySize, SM_MP2);
    cudaFuncSetAttribute(agg_kernel<0>,  cudaFuncAttributeMaxDynamicSharedMemorySize, SMA);
    cudaFuncSetAttribute(agg_kernel<1>,  cudaFuncAttributeMaxDynamicSharedMemorySize, SMA);

    const int* esrc = eidx;
    const int* edst = eidx + EE;

    // ---- prologue ----
    pack_x_kernel<<<(NN*HH)/256, 256>>>(x);
    fold_M_kernel<<<128, 128>>>(npw, ipw);
    fold_vec_kernel<<<1, 128>>>(lpw, npb, lpb, remb, ipw, ipb);
    pack_w128<<<dim3(64, LL), 256>>>(w1, p_w1b);
    pack_w128<<<dim3(64, LL), 256>>>(w2, p_w2b);
    pack_w256<<<dim3(128, LL), 256>>>(mp2w, p_mp2b);
    zero_cnt_kernel<<<(NN + 255)/256, 256>>>();
    count_kernel<<<MROWS/256, 256>>>(nodes);
    inv_kernel<<<(NN + 255)/256, 256>>>();
    zero_xagg_kernel<<<(NN*HH)/256, 256>>>();

    // ---- init projection over distinct nodes: y0 = x @ M ----
    ygemm_pers<<<NSM, NT, SM_Y>>>(p_xph, p_xpl, p_Mb, p_y0);

    // ---- layers ----
    for (int l = 0; l < LL; l++) {
        if (l == 0)
            agg_kernel<0><<<SS, 128, SMA>>>(nullptr, hout, p_zph, p_zpl, esrc, edst,
                                            eptr, geps, nullptr, nullptr,
                                            nodes, logp, rootl, l);
        else
            agg_kernel<1><<<SS, 128, SMA>>>(p_u, hout, p_zph, p_zpl, esrc, edst,
                                            eptr, geps, bng + (l-1)*HH, bnb + (l-1)*HH,
                                            nullptr, nullptr, nullptr, l);

        layer12_kernel<<<NSM, NT, SM_L12>>>(p_w1b + (size_t)l*32768,
                                            p_w2b + (size_t)l*32768,
                                            b1 + l*HH, b2 + l*HH, nodes);

        pack_xagg_kernel<<<(NN*HH)/256, 256>>>();

        // y2 = (xagg*inv) @ Wmp2_half1 over distinct nodes
        ygemm_pers<<<NSM, NT, SM_Y>>>(p_xah, p_xal,
                                      p_mp2b + (size_t)l*65536 + 32768, p_y2);

        mp2_kernel<<<NSM, NT, SM_MP2>>>(p_mp2b + (size_t)l*65536,
                                        mp2b + l*HH, nodes, p_u);
    }

    // ---- final BN apply ----
    bn_apply_kernel<<<(MROWS*HH)/256, 256>>>(p_u, hout, bng + (LL-1)*HH, bnb + (LL-1)*HH);
}

// round 13
// speedup vs baseline: 1.0578x; 1.0578x over previous
#include <cuda_runtime.h>
#include <cuda_bf16.h>

#define NN     50000
#define SS     2048
#define KK     64
#define HH     128
#define EE     524288
#define LL     5
#define MROWS  (SS*KK)      // 131072
#define PL     34816        // full smem plane: 128 rows x 272B
#define APL64  17408        // 64-row plane
#define NSM    148
#define NT     256          // threads per persistent GEMM CTA (8 warps, 32x32 warp tiles)

typedef unsigned short u16;
typedef unsigned int   u32;

// ---------------- scratch (device globals; no allocations) ----------------
__device__ u16 g_Mb[2*16384];
__device__ u16 g_w1b[LL*2*16384];
__device__ u16 g_w2b[LL*2*16384];
__device__ u16 g_mp2b[LL*4*16384];
__device__ float g_vlogp[HH];
__device__ float g_bias0[HH];
__device__ float g_root[2*HH];
__device__ u16 g_xph[NN*HH],    g_xpl[NN*HH];
__device__ u16 g_zph[MROWS*HH], g_zpl[MROWS*HH];
__device__ u16 g_z2h[MROWS*HH], g_z2l[MROWS*HH];
__device__ u16 g_xah[NN*HH],    g_xal[NN*HH];
__device__ float g_u[MROWS*HH];
__device__ float g_xagg[NN*HH];
__device__ float g_inv[NN];
__device__ int   g_cnt[NN];
__device__ float g_stats[2*HH];

// ---------------- helpers ----------------
__device__ __forceinline__ void splitf(float v, u16& h, u16& l) {
    __nv_bfloat16 hb = __float2bfloat16_rn(v);
    __nv_bfloat16 lb = __float2bfloat16_rn(v - __bfloat162float(hb));
    h = __bfloat16_as_ushort(hb);
    l = __bfloat16_as_ushort(lb);
}
__device__ __forceinline__ void pack2(float v0, float v1, u32& hi, u32& lo) {
    u16 h0, l0, h1, l1;
    splitf(v0, h0, l0); splitf(v1, h1, l1);
    hi = (u32)h0 | ((u32)h1 << 16);
    lo = (u32)l0 | ((u32)l1 << 16);
}
__device__ __forceinline__ u32 smem_u32(const void* p) {
    u32 a;
    asm("{ .reg .u64 t; cvta.to.shared.u64 t, %1; cvt.u32.u64 %0, t; }" : "=r"(a) : "l"(p));
    return a;
}

#define CP16(dst, src) \
    asm volatile("cp.async.cg.shared.global [%0], [%1], 16;" :: "r"(dst), "l"(src) : "memory")
#define CPCOMMIT() asm volatile("cp.async.commit_group;" ::: "memory")
#define CPWAIT(n)  asm volatile("cp.async.wait_group %0;" :: "n"(n) : "memory")

#define LDSM4(R0,R1,R2,R3,ADDR) \
    asm volatile("ldmatrix.sync.aligned.m8n8.x4.shared.b16 {%0,%1,%2,%3}, [%4];" \
        : "=r"(R0),"=r"(R1),"=r"(R2),"=r"(R3) : "r"(ADDR))

#define MMA_BF16(C, A0,A1,A2,A3, B0,B1) \
    asm volatile("mma.sync.aligned.m16n8k16.row.col.f32.bf16.bf16.f32 " \
        "{%0,%1,%2,%3},{%4,%5,%6,%7},{%8,%9},{%0,%1,%2,%3};" \
        : "+f"(C[0]),"+f"(C[1]),"+f"(C[2]),"+f"(C[3]) \
        : "r"(A0),"r"(A1),"r"(A2),"r"(A3),"r"(B0),"r"(B1))

// ---- 64-row 3-term core, 8-warp layout (warp tile 32m x 32n) ----
// A slot: hi@aB, lo@aB+APL64. B planes: hi@bB, lo@bB+PL.
__device__ __forceinline__ void gemm64w8(u32 aB, u32 bB,
                                         const u32* ar, const u32* br,
                                         float c[2][4][4])
{
    #pragma unroll
    for (int ks = 0; ks < 8; ks++) {
        const u32 ko = ks*32;
        unsigned ah[2][4], al[2][4], bh[2][4], bl[2][4];
        LDSM4(ah[0][0],ah[0][1],ah[0][2],ah[0][3], aB + ar[0] + ko);
        LDSM4(ah[1][0],ah[1][1],ah[1][2],ah[1][3], aB + ar[1] + ko);
        LDSM4(al[0][0],al[0][1],al[0][2],al[0][3], aB + APL64 + ar[0] + ko);
        LDSM4(al[1][0],al[1][1],al[1][2],al[1][3], aB + APL64 + ar[1] + ko);
        LDSM4(bh[0][0],bh[0][1],bh[0][2],bh[0][3], bB + br[0] + ko);
        LDSM4(bh[1][0],bh[1][1],bh[1][2],bh[1][3], bB + br[1] + ko);
        // term1: ah * wh (16 independent MMAs)
        #pragma unroll
        for (int mf = 0; mf < 2; mf++)
            #pragma unroll
            for (int g = 0; g < 2; g++) {
                MMA_BF16(c[mf][2*g+0], ah[mf][0],ah[mf][1],ah[mf][2],ah[mf][3],
                         bh[g][0],bh[g][2]);
                MMA_BF16(c[mf][2*g+1], ah[mf][0],ah[mf][1],ah[mf][2],ah[mf][3],
                         bh[g][1],bh[g][3]);
            }
        LDSM4(bl[0][0],bl[0][1],bl[0][2],bl[0][3], bB + PL + br[0] + ko);
        LDSM4(bl[1][0],bl[1][1],bl[1][2],bl[1][3], bB + PL + br[1] + ko);
        // term2: al * wh
        #pragma unroll
        for (int mf = 0; mf < 2; mf++)
            #pragma unroll
            for (int g = 0; g < 2; g++) {
                MMA_BF16(c[mf][2*g+0], al[mf][0],al[mf][1],al[mf][2],al[mf][3],
                         bh[g][0],bh[g][2]);
                MMA_BF16(c[mf][2*g+1], al[mf][0],al[mf][1],al[mf][2],al[mf][3],
                         bh[g][1],bh[g][3]);
            }
        // term3: ah * wl
        #pragma unroll
        for (int mf = 0; mf < 2; mf++)
            #pragma unroll
            for (int g = 0; g < 2; g++) {
                MMA_BF16(c[mf][2*g+0], ah[mf][0],ah[mf][1],ah[mf][2],ah[mf][3],
                         bl[g][0],bl[g][2]);
                MMA_BF16(c[mf][2*g+1], ah[mf][0],ah[mf][1],ah[mf][2],ah[mf][3],
                         bl[g][1],bl[g][3]);
            }
    }
}

#define ZERO_C24(c) { _Pragma("unroll") for (int i=0;i<2;i++) _Pragma("unroll") \
    for (int j=0;j<4;j++) _Pragma("unroll") for (int q=0;q<4;q++) (c)[i][j][q]=0.f; }

// ---- fragment address setup: warp = wm + 2*wn; wm in {0,1}, wn in {0..3} ----
__device__ __forceinline__ void frag_a(int lane, int wm, u32* ar) {
    #pragma unroll
    for (int mf = 0; mf < 2; mf++) {
        int row = wm*32 + mf*16 + (lane & 15);
        ar[mf] = row*272 + (lane>>4)*16;
    }
}
__device__ __forceinline__ void frag_b(int lane, int wn, u32* br) {
    #pragma unroll
    for (int g = 0; g < 2; g++) {
        int row = wn*32 + g*16 + ((lane>>3)&1)*8 + (lane&7);
        br[g] = row*272 + (lane>>4)*16;
    }
}

// ---- smem loaders (256 threads; caller commits) ----
__device__ __forceinline__ void loadW(u32 dst, const u16* blob, int tid) {
    #pragma unroll
    for (int it = 0; it < 16; it++) {
        int ch = tid + it*NT;                  // 4096 chunks
        int pl = ch >> 11, rem = ch & 2047, r = rem >> 4, q = rem & 15;
        CP16(dst + pl*PL + r*272 + q*16, blob + (size_t)pl*16384 + r*128 + q*8);
    }
}
__device__ __forceinline__ void loadA64(u32 dst, const u16* Ah, const u16* Al,
                                        int rowbase, const int* idx, int tid) {
    #pragma unroll
    for (int it = 0; it < 8; it++) {
        int ch = tid + it*NT;                  // 2048 chunks
        int pl = ch >> 10, rem = ch & 1023, r = rem >> 4, q = rem & 15;
        int row = idx ? idx[rowbase + r] : (rowbase + r);
        CP16(dst + pl*APL64 + r*272 + q*16, (pl ? Al : Ah) + (size_t)row*HH + q*8);
    }
}

// ---------------- packing kernels ----------------
__global__ void pack_x_kernel(const float* __restrict__ x) {
    int idx = blockIdx.x*256 + threadIdx.x;
    u16 h, l; splitf(x[idx], h, l);
    g_xph[idx] = h; g_xpl[idx] = l;
}
__global__ void fold_M_kernel(const float* __restrict__ npw, const float* __restrict__ ipw) {
    int k = blockIdx.x, n = threadIdx.x;
    float s = 0.f;
    for (int c = 0; c < HH; c++) s += npw[k*HH + c] * ipw[c*HH + n];
    u16 h, l; splitf(s, h, l);
    g_Mb[n*128 + k] = h; g_Mb[16384 + n*128 + k] = l;
}
__global__ void fold_vec_kernel(const float* __restrict__ lpw, const float* __restrict__ npb,
                                const float* __restrict__ lpb, const float* __restrict__ remb,
                                const float* __restrict__ ipw, const float* __restrict__ ipb) {
    int j = threadIdx.x;
    float v = 0.f, b = ipb[j], r0 = 0.f, r1 = 0.f;
    for (int k = 0; k < HH; k++) {
        float wa = ipw[k*HH + j];
        float wb = ipw[(HH + k)*HH + j];
        float wc = ipw[(2*HH + k)*HH + j];
        v  += lpw[k] * wb;
        b  += npb[k] * wa + lpb[k] * wb;
        r0 += remb[k] * wc;
        r1 += remb[HH + k] * wc;
    }
    g_vlogp[j] = v; g_bias0[j] = b; g_root[j] = r0; g_root[HH + j] = r1;
}
// blockIdx.z: 0 -> w1 to g_w1b, 1 -> w2 to g_w2b
__global__ void pack_w12(const float* __restrict__ W1, const float* __restrict__ W2) {
    int l = blockIdx.y;
    int idx = blockIdx.x*256 + threadIdx.x;
    int k = idx >> 7, n = idx & 127;
    const float* W = blockIdx.z ? W2 : W1;
    u16* out = blockIdx.z ? g_w2b : g_w1b;
    u16 h, lo; splitf(W[(size_t)l*16384 + idx], h, lo);
    out[(size_t)l*32768 + n*128 + k] = h;
    out[(size_t)l*32768 + 16384 + n*128 + k] = lo;
}
__global__ void pack_w256(const float* __restrict__ W, u16* __restrict__ out) {
    int l = blockIdx.y;
    int idx = blockIdx.x*256 + threadIdx.x;
    int kg = idx >> 7, n = idx & 127;
    int half = kg >> 7, kl = kg & 127;
    u16 h, lo; splitf(W[(size_t)l*32768 + idx], h, lo);
    out[(size_t)l*65536 + half*32768 + n*128 + kl] = h;
    out[(size_t)l*65536 + half*32768 + 16384 + n*128 + kl] = lo;
}

// ---------------- counts ----------------
__global__ void zero_all_kernel() {        // covers NN*HH
    int i = blockIdx.x*blockDim.x + threadIdx.x;
    g_xagg[i] = 0.f;
    if (i < NN) g_cnt[i] = 0;
    if (i < 2*HH) g_stats[i] = 0.f;
}
__global__ void count_kernel(const int* __restrict__ nodes) {
    int i = blockIdx.x*blockDim.x + threadIdx.x;
    if (i < MROWS) atomicAdd(&g_cnt[nodes[i]], 1);
}
__global__ void inv_kernel() {
    int i = blockIdx.x*blockDim.x + threadIdx.x;
    if (i < NN) g_inv[i] = 1.f / (float)max(g_cnt[i], 1);
}
__global__ void pack_xagg_kernel() {
    int idx = blockIdx.x*256 + threadIdx.x;
    int row = idx >> 7;
    float v = g_xagg[idx] * g_inv[row];
    u16 h, l; splitf(v, h, l);
    g_xah[idx] = h; g_xal[idx] = l;
    g_xagg[idx] = 0.f;
    if (blockIdx.x == 0 && threadIdx.x < 2*HH) g_stats[threadIdx.x] = 0.f;
}

// ---------------- persistent init GEMM (64-row tiles, 8 warps) ----------------
__global__ void __launch_bounds__(NT, 1)
init_gemm(const float* __restrict__ logp, const int* __restrict__ rootl,
          const int* __restrict__ nodes, float* __restrict__ Cout)
{
    extern __shared__ __align__(16) char sm[];
    const u32 sb = smem_u32(sm);          // M planes [0,2PL); A slots 2PL + s*PL
    const int tid = threadIdx.x, lane = tid & 31, warp = tid >> 5;
    const int wm = warp & 1, wn = warp >> 1;

    loadW(sb, g_Mb, tid);
    loadA64(sb + 2*PL, g_xph, g_xpl, blockIdx.x * 64, nodes, tid);
    CPCOMMIT();

    u32 ar[2], br[2];
    frag_a(lane, wm, ar);
    frag_b(lane, wn, br);
    const int gid = lane >> 2, tig = lane & 3;

    int j = 0;
    for (int t = blockIdx.x; t < MROWS/64; t += NSM, j++) {
        int tn = t + NSM;
        if (tn < MROWS/64) {
            loadA64(sb + 2*PL + ((j+1)&1)*PL, g_xph, g_xpl, tn*64, nodes, tid);
            CPCOMMIT();
            CPWAIT(1);
        } else {
            CPWAIT(0);
        }
        __syncthreads();

        float c[2][4][4]; ZERO_C24(c);
        gemm64w8(sb + 2*PL + (j&1)*PL, sb, ar, br, c);

        int brow = t * 64;
        #pragma unroll
        for (int mf = 0; mf < 2; mf++) {
            #pragma unroll
            for (int half = 0; half < 2; half++) {
                int gr = brow + wm*32 + mf*16 + half*8 + gid;
                int sub = gr >> 6;
                float lp = logp[sub];
                int isr = ((gr & 63) == rootl[sub]) ? 1 : 0;
                #pragma unroll
                for (int nf = 0; nf < 4; nf++) {
                    int n0 = wn*32 + nf*8 + tig*2;
                    float v0 = c[mf][nf][half*2+0] + g_bias0[n0]
                             + lp * g_vlogp[n0]   + g_root[isr*HH + n0];
                    float v1 = c[mf][nf][half*2+1] + g_bias0[n0+1]
                             + lp * g_vlogp[n0+1] + g_root[isr*HH + n0+1];
                    float2 o; o.x = v0; o.y = v1;
                    *(float2*)(Cout + (size_t)gr*HH + n0) = o;
                }
            }
        }
        __syncthreads();
    }
}

// ---------------- persistent fused layer kernel (64-row tiles, 8 warps) ----------------
__global__ void __launch_bounds__(NT, 1)
layer12_kernel(const u16* __restrict__ w1b, const u16* __restrict__ w2b,
               const float* __restrict__ b1, const float* __restrict__ b2,
               const int* __restrict__ aidx)
{
    extern __shared__ __align__(16) char sm[];
    const u32 sb = smem_u32(sm);          // W1 [0,2PL); W2 [2PL,4PL); A slots 4PL + s*PL
    const int tid = threadIdx.x, lane = tid & 31, warp = tid >> 5;
    const int wm = warp & 1, wn = warp >> 1;

    loadW(sb, w1b, tid);
    loadW(sb + 2*PL, w2b, tid);
    loadA64(sb + 4*PL, g_zph, g_zpl, blockIdx.x * 64, nullptr, tid);
    CPCOMMIT();

    u32 ar[2], br[2];
    frag_a(lane, wm, ar);
    frag_b(lane, wn, br);
    const int gid = lane >> 2, tig = lane & 3;

    int j = 0;
    for (int t = blockIdx.x; t < MROWS/64; t += NSM, j++) {
        int tn = t + NSM;
        if (tn < MROWS/64) {
            loadA64(sb + 4*PL + ((j+1)&1)*PL, g_zph, g_zpl, tn*64, nullptr, tid);
            CPCOMMIT();
            CPWAIT(1);
        } else {
            CPWAIT(0);
        }
        __syncthreads();

        const u32 aslot = sb + 4*PL + (j&1)*PL;
        float c[2][4][4]; ZERO_C24(c);
        gemm64w8(aslot, sb, ar, br, c);     // z @ W1
        __syncthreads();                     // all z reads done

        char* aptr = sm + (4*PL + (j&1)*PL);
        #pragma unroll
        for (int mf = 0; mf < 2; mf++) {
            #pragma unroll
            for (int half = 0; half < 2; half++) {
                int m = wm*32 + mf*16 + half*8 + gid;
                #pragma unroll
                for (int nf = 0; nf < 4; nf++) {
                    int n0 = wn*32 + nf*8 + tig*2;
                    float v0 = fmaxf(c[mf][nf][half*2+0] + b1[n0],   0.f);
                    float v1 = fmaxf(c[mf][nf][half*2+1] + b1[n0+1], 0.f);
                    u32 hi, lo; pack2(v0, v1, hi, lo);
                    u32 off = m*272 + n0*2;
                    *(u32*)(aptr + off)         = hi;
                    *(u32*)(aptr + APL64 + off) = lo;
                }
            }
        }
        __syncthreads();

        ZERO_C24(c);
        gemm64w8(aslot, sb + 2*PL, ar, br, c);   // t @ W2

        int brow = t * 64;
        #pragma unroll
        for (int mf = 0; mf < 2; mf++) {
            #pragma unroll
            for (int half = 0; half < 2; half++) {
                int gr = brow + wm*32 + mf*16 + half*8 + gid;
                int nd = aidx[gr];
                #pragma unroll
                for (int nf = 0; nf < 4; nf++) {
                    int n0 = wn*32 + nf*8 + tig*2;
                    float v0 = c[mf][nf][half*2+0] + b2[n0];
                    float v1 = c[mf][nf][half*2+1] + b2[n0+1];
                    u32 hi, lo; pack2(v0, v1, hi, lo);
                    *(u32*)(g_z2h + (size_t)gr*HH + n0) = hi;
                    *(u32*)(g_z2l + (size_t)gr*HH + n0) = lo;
                    atomicAdd(&g_xagg[(size_t)nd*HH + n0],     v0);
                    atomicAdd(&g_xagg[(size_t)nd*HH + n0 + 1], v1);
                }
            }
        }
        __syncthreads();
    }
}

// ---------------- persistent mp2 kernel (64-row tiles, 8 warps, K=256) ----------------
__global__ void __launch_bounds__(NT, 1)
mp2_kernel(const u16* __restrict__ blob, const float* __restrict__ bias,
           const int* __restrict__ aidx, float* __restrict__ uout)
{
    extern __shared__ __align__(16) char sm[];
    const u32 sb = smem_u32(sm);          // Wh0 [0,2PL); Wh1 [2PL,4PL); slotZ 4PL; slotX 5PL
    const int tid = threadIdx.x, lane = tid & 31, warp = tid >> 5;
    const int wm = warp & 1, wn = warp >> 1;

    loadW(sb, blob, tid);
    loadW(sb + 2*PL, blob + 32768, tid);
    loadA64(sb + 4*PL, g_z2h, g_z2l, blockIdx.x * 64, nullptr, tid);
    CPCOMMIT();

    u32 ar[2], br[2];
    frag_a(lane, wm, ar);
    frag_b(lane, wn, br);
    const int gid = lane >> 2, tig = lane & 3;

    float s0[4], s1[4], q0[4], q1[4];
    #pragma unroll
    for (int nf = 0; nf < 4; nf++) { s0[nf]=0.f; s1[nf]=0.f; q0[nf]=0.f; q1[nf]=0.f; }

    for (int t = blockIdx.x; t < MROWS/64; t += NSM) {
        loadA64(sb + 5*PL, g_xah, g_xal, t*64, aidx, tid);   // gathered xagg chunk
        CPCOMMIT();
        CPWAIT(1);                       // z2 chunk ready
        __syncthreads();

        float c[2][4][4]; ZERO_C24(c);
        gemm64w8(sb + 4*PL, sb, ar, br, c);         // z2 @ W[half0]
        __syncthreads();                             // slotZ reads done

        int tn = t + NSM;
        if (tn < MROWS/64) {
            loadA64(sb + 4*PL, g_z2h, g_z2l, tn*64, nullptr, tid);
            CPCOMMIT();
            CPWAIT(1);                  // xa chunk ready
        } else {
            CPWAIT(0);
        }
        __syncthreads();

        gemm64w8(sb + 5*PL, sb + 2*PL, ar, br, c);  // += xa @ W[half1]

        int brow = t * 64;
        #pragma unroll
        for (int mf = 0; mf < 2; mf++) {
            #pragma unroll
            for (int half = 0; half < 2; half++) {
                int gr = brow + wm*32 + mf*16 + half*8 + gid;
                #pragma unroll
                for (int nf = 0; nf < 4; nf++) {
                    int n0 = wn*32 + nf*8 + tig*2;
                    float v0 = fmaxf(c[mf][nf][half*2+0] + bias[n0],   0.f);
                    float v1 = fmaxf(c[mf][nf][half*2+1] + bias[n0+1], 0.f);
                    float2 o; o.x = v0; o.y = v1;
                    *(float2*)(uout + (size_t)gr*HH + n0) = o;
                    s0[nf] += v0; s1[nf] += v1;
                    q0[nf] += v0*v0; q1[nf] += v1*v1;
                }
            }
        }
        __syncthreads();                             // protect slotX for next tile
    }

    #pragma unroll
    for (int nf = 0; nf < 4; nf++) {
        #pragma unroll
        for (int off = 4; off < 32; off <<= 1) {
            s0[nf] += __shfl_xor_sync(0xFFFFFFFFu, s0[nf], off);
            s1[nf] += __shfl_xor_sync(0xFFFFFFFFu, s1[nf], off);
            q0[nf] += __shfl_xor_sync(0xFFFFFFFFu, q0[nf], off);
            q1[nf] += __shfl_xor_sync(0xFFFFFFFFu, q1[nf], off);
        }
    }
    if (gid == 0) {
        #pragma unroll
        for (int nf = 0; nf < 4; nf++) {
            int n0 = wn*32 + nf*8 + tig*2;
            atomicAdd(&g_stats[n0],      s0[nf]);
            atomicAdd(&g_stats[n0+1],    s1[nf]);
            atomicAdd(&g_stats[HH+n0],   q0[nf]);
            atomicAdd(&g_stats[HH+n0+1], q1[nf]);
        }
    }
}

// ---------------- agg: 256 threads, dual edge accumulators ----------------
// FUSE_BN==0: h = H (pass-through); FUSE_BN==1: h = bn(u)+H, writes H back.
template<int FUSE_BN>
__global__ void __launch_bounds__(256)
agg_kernel(const float* __restrict__ u, float* __restrict__ H,
           u16* __restrict__ zph, u16* __restrict__ zpl,
           const int* __restrict__ esrc, const int* __restrict__ edst,
           const int* __restrict__ eptr, const float* __restrict__ geps,
           const float* __restrict__ gamma, const float* __restrict__ beta,
           int l)
{
    extern __shared__ float fsm[];
    float* hsm  = fsm;                  // [KK][HH]
    float* acc0 = fsm + KK*HH;          // [KK][HH]
    float* acc1 = fsm + 2*KK*HH;        // [KK][HH]
    __shared__ int se[2][128], de[2][128];
    const int s = blockIdx.x;
    const int tid = threadIdx.x;        // 256
    const int grp = tid >> 7, col = tid & 127;
    const float eps1 = 1.f + geps[l];
    const size_t base = (size_t)s * KK;

    float g = 0.f, bt = 0.f, mu = 0.f;
    if (FUSE_BN) {
        const float invM = 1.f / (float)MROWS;
        mu = g_stats[col] * invM;
        float var = g_stats[HH + col] * invM - mu*mu;
        g = gamma[col] * rsqrtf(var + 1e-5f);
        bt = beta[col];
    }

    // rows grp*32 .. grp*32+31
    #pragma unroll 4
    for (int r = grp*32; r < grp*32 + 32; r++) {
        float hv;
        if (FUSE_BN) {
            float uv = u[(base + r)*HH + col];
            hv = (uv - mu) * g + bt + H[(base + r)*HH + col];
            H[(base + r)*HH + col] = hv;
        } else {
            hv = H[(base + r)*HH + col];
        }
        hsm[r*HH + col]  = hv;
        acc0[r*HH + col] = eps1 * hv;
        acc1[r*HH + col] = 0.f;
    }
    __syncthreads();

    const int e0 = eptr[s], e1 = eptr[s+1];
    const int etot = e1 - e0;
    const int nh0 = (etot + 1) >> 1;               // group0 edge count (>= group1)
    const int gb = (grp == 0) ? e0 : e0 + nh0;
    const int gcnt = (grp == 0) ? nh0 : etot - nh0;
    float* accg = (grp == 0) ? acc0 : acc1;
    const int nbatch = (nh0 + 127) >> 7;           // uniform across groups

    for (int b = 0; b < nbatch; b++) {
        int off = b*128;
        int ne = min(128, gcnt - off);             // may be <=0 for group1 tail
        if (col < ne) {
            se[grp][col] = esrc[gb + off + col];
            de[grp][col] = edst[gb + off + col];
        }
        __syncthreads();
        for (int i = 0; i < ne; i++)
            accg[de[grp][i]*HH + col] += hsm[se[grp][i]*HH + col];
        __syncthreads();
    }

    // merge + split to planes
    #pragma unroll 4
    for (int r = grp*32; r < grp*32 + 32; r++) {
        float v = acc0[r*HH + col] + acc1[r*HH + col];
        u16 h, lo; splitf(v, h, lo);
        zph[(base + r)*HH + col] = h;
        zpl[(base + r)*HH + col] = lo;
    }
}

// ---------------- final batchnorm apply ----------------
__global__ void bn_apply_kernel(const float* __restrict__ u, float* __restrict__ h,
                                const float* __restrict__ gamma, const float* __restrict__ beta) {
    int idx = blockIdx.x*blockDim.x + threadIdx.x;
    int c = idx & 127;
    const float invM = 1.f / (float)MROWS;
    float mu  = g_stats[c] * invM;
    float var = g_stats[HH + c] * invM - mu*mu;
    float g = gamma[c] * rsqrtf(var + 1e-5f);
    h[idx] = (u[idx] - mu) * g + beta[c] + h[idx];
}

// ---------------- launch ----------------
extern "C" void kernel_launch(void* const* d_in, const int* in_sizes, int n_in,
                              void* d_out, int out_size) {
    const float* x    = (const float*)d_in[0];
    const float* logp = (const float*)d_in[1];
    const float* npw  = (const float*)d_in[2];
    const float* npb  = (const float*)d_in[3];
    const float* lpw  = (const float*)d_in[4];
    const float* lpb  = (const float*)d_in[5];
    const float* remb = (const float*)d_in[6];
    const float* ipw  = (const float*)d_in[7];
    const float* ipb  = (const float*)d_in[8];
    const float* geps = (const float*)d_in[9];
    const float* w1   = (const float*)d_in[10];
    const float* b1   = (const float*)d_in[11];
    const float* w2   = (const float*)d_in[12];
    const float* b2   = (const float*)d_in[13];
    const float* mp2w = (const float*)d_in[14];
    const float* mp2b = (const float*)d_in[15];
    const float* bng  = (const float*)d_in[16];
    const float* bnb  = (const float*)d_in[17];
    const int* nodes  = (const int*)d_in[18];
    const int* rootl  = (const int*)d_in[19];
    const int* eidx   = (const int*)d_in[20];
    const int* eptr   = (const int*)d_in[21];
    float* hout = (float*)d_out;

    float *p_u;
    u16 *p_zph, *p_zpl, *p_w1b, *p_w2b, *p_mp2b;
    cudaGetSymbolAddress((void**)&p_u, g_u);
    cudaGetSymbolAddress((void**)&p_zph, g_zph);
    cudaGetSymbolAddress((void**)&p_zpl, g_zpl);
    cudaGetSymbolAddress((void**)&p_w1b, g_w1b);
    cudaGetSymbolAddress((void**)&p_w2b, g_w2b);
    cudaGetSymbolAddress((void**)&p_mp2b, g_mp2b);

    const int SM_INIT = 4*PL;             // 139264
    const int SM_BIG  = 6*PL;             // 208896
    const int SMA = 3*KK*HH*4;            // 98304 (hsm + 2 accumulators)
    cudaFuncSetAttribute(init_gemm,      cudaFuncAttributeMaxDynamicSharedMemorySize, SM_INIT);
    cudaFuncSetAttribute(layer12_kernel, cudaFuncAttributeMaxDynamicSharedMemorySize, SM_BIG);
    cudaFuncSetAttribute(mp2_kernel,     cudaFuncAttributeMaxDynamicSharedMemorySize, SM_BIG);
    cudaFuncSetAttribute(agg_kernel<0>,  cudaFuncAttributeMaxDynamicSharedMemorySize, SMA);
    cudaFuncSetAttribute(agg_kernel<1>,  cudaFuncAttributeMaxDynamicSharedMemorySize, SMA);

    const int* esrc = eidx;
    const int* edst = eidx + EE;

    // ---- prologue (ordered so init_gemm is the 6th launch for ncu -s 5) ----
    pack_x_kernel<<<(NN*HH)/256, 256>>>(x);                       // 1
    fold_M_kernel<<<128, 128>>>(npw, ipw);                        // 2
    fold_vec_kernel<<<1, 128>>>(lpw, npb, lpb, remb, ipw, ipb);   // 3
    pack_w12<<<dim3(64, LL, 2), 256>>>(w1, w2);                   // 4
    pack_w256<<<dim3(128, LL), 256>>>(mp2w, p_mp2b);              // 5
    init_gemm<<<NSM, NT, SM_INIT>>>(logp, rootl, nodes, hout);    // 6 <- profiled
    zero_all_kernel<<<(NN*HH)/256, 256>>>();                      // 7
    count_kernel<<<MROWS/256, 256>>>(nodes);                      // 8
    inv_kernel<<<(NN + 255)/256, 256>>>();                        // 9

    // ---- layers ----
    for (int l = 0; l < LL; l++) {
        if (l == 0)
            agg_kernel<0><<<SS, 256, SMA>>>(nullptr, hout, p_zph, p_zpl, esrc, edst,
                                            eptr, geps, nullptr, nullptr, l);
        else
            agg_kernel<1><<<SS, 256, SMA>>>(p_u, hout, p_zph, p_zpl, esrc, edst,
                                            eptr, geps, bng + (l-1)*HH, bnb + (l-1)*HH, l);

        layer12_kernel<<<NSM, NT, SM_BIG>>>(p_w1b + (size_t)l*32768,
                                            p_w2b + (size_t)l*32768,
                                            b1 + l*HH, b2 + l*HH, nodes);

        pack_xagg_kernel<<<(NN*HH)/256, 256>>>();

        mp2_kernel<<<NSM, NT, SM_BIG>>>(p_mp2b + (size_t)l*65536,
                                        mp2b + l*HH, nodes, p_u);
    }

    // ---- final BN apply ----
    bn_apply_kernel<<<(MROWS*HH)/256, 256>>>(p_u, hout, bng + (LL-1)*HH, bnb + (LL-1)*HH);
}

// round 14
// speedup vs baseline: 1.1810x; 1.1165x over previous
#include <cuda_runtime.h>
#include <cuda_bf16.h>

#define NN     50000
#define SS     2048
#define KK     64
#define HH     128
#define EE     524288
#define LL     5
#define MROWS  (SS*KK)      // 131072
#define PL     34816        // full smem plane: 128 rows x 272B
#define APL64  17408        // 64-row plane
#define NSM    148
#define NT     256          // threads per persistent GEMM CTA (8 warps, 32x32 warp tiles)

typedef unsigned short u16;
typedef unsigned int   u32;

// ---------------- scratch (device globals; no allocations) ----------------
__device__ u16 g_Mb[2*16384];
__device__ u16 g_w1b[LL*2*16384];
__device__ u16 g_w2b[LL*2*16384];
__device__ u16 g_mp2b[LL*4*16384];
__device__ float g_vlogp[HH];
__device__ float g_bias0[HH];
__device__ float g_root[2*HH];
__device__ u16 g_xph[NN*HH],    g_xpl[NN*HH];
__device__ u16 g_zph[MROWS*HH], g_zpl[MROWS*HH];
__device__ u16 g_z2h[MROWS*HH], g_z2l[MROWS*HH];
__device__ u16 g_xah[NN*HH],    g_xal[NN*HH];
__device__ float g_u[MROWS*HH];
__device__ float g_xagg[NN*HH];
__device__ float g_inv[NN];
__device__ int   g_cnt[NN];
__device__ float g_stats[2*HH];
__device__ int   g_esrt[EE];             // edge sources, sorted by dst per subgraph
__device__ int   g_rowptr[SS*(KK+1)];    // per-subgraph CSR row pointers

// ---------------- helpers ----------------
__device__ __forceinline__ void splitf(float v, u16& h, u16& l) {
    __nv_bfloat16 hb = __float2bfloat16_rn(v);
    __nv_bfloat16 lb = __float2bfloat16_rn(v - __bfloat162float(hb));
    h = __bfloat16_as_ushort(hb);
    l = __bfloat16_as_ushort(lb);
}
__device__ __forceinline__ void pack2(float v0, float v1, u32& hi, u32& lo) {
    u16 h0, l0, h1, l1;
    splitf(v0, h0, l0); splitf(v1, h1, l1);
    hi = (u32)h0 | ((u32)h1 << 16);
    lo = (u32)l0 | ((u32)l1 << 16);
}
__device__ __forceinline__ u32 smem_u32(const void* p) {
    u32 a;
    asm("{ .reg .u64 t; cvta.to.shared.u64 t, %1; cvt.u32.u64 %0, t; }" : "=r"(a) : "l"(p));
    return a;
}

#define CP16(dst, src) \
    asm volatile("cp.async.cg.shared.global [%0], [%1], 16;" :: "r"(dst), "l"(src) : "memory")
#define CPCOMMIT() asm volatile("cp.async.commit_group;" ::: "memory")
#define CPWAIT(n)  asm volatile("cp.async.wait_group %0;" :: "n"(n) : "memory")
#define BARG(id)   asm volatile("bar.sync %0, 128;" :: "r"(id) : "memory")

#define LDSM4(R0,R1,R2,R3,ADDR) \
    asm volatile("ldmatrix.sync.aligned.m8n8.x4.shared.b16 {%0,%1,%2,%3}, [%4];" \
        : "=r"(R0),"=r"(R1),"=r"(R2),"=r"(R3) : "r"(ADDR))

#define MMA_BF16(C, A0,A1,A2,A3, B0,B1) \
    asm volatile("mma.sync.aligned.m16n8k16.row.col.f32.bf16.bf16.f32 " \
        "{%0,%1,%2,%3},{%4,%5,%6,%7},{%8,%9},{%0,%1,%2,%3};" \
        : "+f"(C[0]),"+f"(C[1]),"+f"(C[2]),"+f"(C[3]) \
        : "r"(A0),"r"(A1),"r"(A2),"r"(A3),"r"(B0),"r"(B1))

// ---- 64-row 3-term core, 8-warp layout (warp tile 32m x 32n) ----
__device__ __forceinline__ void gemm64w8(u32 aB, u32 bB,
                                         const u32* ar, const u32* br,
                                         float c[2][4][4])
{
    #pragma unroll
    for (int ks = 0; ks < 8; ks++) {
        const u32 ko = ks*32;
        unsigned ah[2][4], al[2][4], bh[2][4], bl[2][4];
        LDSM4(ah[0][0],ah[0][1],ah[0][2],ah[0][3], aB + ar[0] + ko);
        LDSM4(ah[1][0],ah[1][1],ah[1][2],ah[1][3], aB + ar[1] + ko);
        LDSM4(al[0][0],al[0][1],al[0][2],al[0][3], aB + APL64 + ar[0] + ko);
        LDSM4(al[1][0],al[1][1],al[1][2],al[1][3], aB + APL64 + ar[1] + ko);
        LDSM4(bh[0][0],bh[0][1],bh[0][2],bh[0][3], bB + br[0] + ko);
        LDSM4(bh[1][0],bh[1][1],bh[1][2],bh[1][3], bB + br[1] + ko);
        #pragma unroll
        for (int mf = 0; mf < 2; mf++)
            #pragma unroll
            for (int g = 0; g < 2; g++) {
                MMA_BF16(c[mf][2*g+0], ah[mf][0],ah[mf][1],ah[mf][2],ah[mf][3],
                         bh[g][0],bh[g][2]);
                MMA_BF16(c[mf][2*g+1], ah[mf][0],ah[mf][1],ah[mf][2],ah[mf][3],
                         bh[g][1],bh[g][3]);
            }
        LDSM4(bl[0][0],bl[0][1],bl[0][2],bl[0][3], bB + PL + br[0] + ko);
        LDSM4(bl[1][0],bl[1][1],bl[1][2],bl[1][3], bB + PL + br[1] + ko);
        #pragma unroll
        for (int mf = 0; mf < 2; mf++)
            #pragma unroll
            for (int g = 0; g < 2; g++) {
                MMA_BF16(c[mf][2*g+0], al[mf][0],al[mf][1],al[mf][2],al[mf][3],
                         bh[g][0],bh[g][2]);
                MMA_BF16(c[mf][2*g+1], al[mf][0],al[mf][1],al[mf][2],al[mf][3],
                         bh[g][1],bh[g][3]);
            }
        #pragma unroll
        for (int mf = 0; mf < 2; mf++)
            #pragma unroll
            for (int g = 0; g < 2; g++) {
                MMA_BF16(c[mf][2*g+0], ah[mf][0],ah[mf][1],ah[mf][2],ah[mf][3],
                         bl[g][0],bl[g][2]);
                MMA_BF16(c[mf][2*g+1], ah[mf][0],ah[mf][1],ah[mf][2],ah[mf][3],
                         bl[g][1],bl[g][3]);
            }
    }
}

#define ZERO_C24(c) { _Pragma("unroll") for (int i=0;i<2;i++) _Pragma("unroll") \
    for (int j=0;j<4;j++) _Pragma("unroll") for (int q=0;q<4;q++) (c)[i][j][q]=0.f; }

__device__ __forceinline__ void frag_a(int lane, int wm, u32* ar) {
    #pragma unroll
    for (int mf = 0; mf < 2; mf++) {
        int row = wm*32 + mf*16 + (lane & 15);
        ar[mf] = row*272 + (lane>>4)*16;
    }
}
__device__ __forceinline__ void frag_b(int lane, int wn, u32* br) {
    #pragma unroll
    for (int g = 0; g < 2; g++) {
        int row = wn*32 + g*16 + ((lane>>3)&1)*8 + (lane&7);
        br[g] = row*272 + (lane>>4)*16;
    }
}

// ---- smem loaders (256 threads; caller commits) ----
__device__ __forceinline__ void loadW(u32 dst, const u16* blob, int tid) {
    #pragma unroll
    for (int it = 0; it < 16; it++) {
        int ch = tid + it*NT;
        int pl = ch >> 11, rem = ch & 2047, r = rem >> 4, q = rem & 15;
        CP16(dst + pl*PL + r*272 + q*16, blob + (size_t)pl*16384 + r*128 + q*8);
    }
}
__device__ __forceinline__ void loadA64(u32 dst, const u16* Ah, const u16* Al,
                                        int rowbase, const int* idx, int tid) {
    #pragma unroll
    for (int it = 0; it < 8; it++) {
        int ch = tid + it*NT;
        int pl = ch >> 10, rem = ch & 1023, r = rem >> 4, q = rem & 15;
        int row = idx ? idx[rowbase + r] : (rowbase + r);
        CP16(dst + pl*APL64 + r*272 + q*16, (pl ? Al : Ah) + (size_t)row*HH + q*8);
    }
}

// ---------------- packing kernels ----------------
__global__ void pack_x_kernel(const float* __restrict__ x) {
    int idx = blockIdx.x*256 + threadIdx.x;
    u16 h, l; splitf(x[idx], h, l);
    g_xph[idx] = h; g_xpl[idx] = l;
}
__global__ void fold_M_kernel(const float* __restrict__ npw, const float* __restrict__ ipw) {
    int k = blockIdx.x, n = threadIdx.x;
    float s = 0.f;
    for (int c = 0; c < HH; c++) s += npw[k*HH + c] * ipw[c*HH + n];
    u16 h, l; splitf(s, h, l);
    g_Mb[n*128 + k] = h; g_Mb[16384 + n*128 + k] = l;
}
__global__ void fold_vec_kernel(const float* __restrict__ lpw, const float* __restrict__ npb,
                                const float* __restrict__ lpb, const float* __restrict__ remb,
                                const float* __restrict__ ipw, const float* __restrict__ ipb) {
    int j = threadIdx.x;
    float v = 0.f, b = ipb[j], r0 = 0.f, r1 = 0.f;
    for (int k = 0; k < HH; k++) {
        float wa = ipw[k*HH + j];
        float wb = ipw[(HH + k)*HH + j];
        float wc = ipw[(2*HH + k)*HH + j];
        v  += lpw[k] * wb;
        b  += npb[k] * wa + lpb[k] * wb;
        r0 += remb[k] * wc;
        r1 += remb[HH + k] * wc;
    }
    g_vlogp[j] = v; g_bias0[j] = b; g_root[j] = r0; g_root[HH + j] = r1;
}
__global__ void pack_w12(const float* __restrict__ W1, const float* __restrict__ W2) {
    int l = blockIdx.y;
    int idx = blockIdx.x*256 + threadIdx.x;
    int k = idx >> 7, n = idx & 127;
    const float* W = blockIdx.z ? W2 : W1;
    u16* out = blockIdx.z ? g_w2b : g_w1b;
    u16 h, lo; splitf(W[(size_t)l*16384 + idx], h, lo);
    out[(size_t)l*32768 + n*128 + k] = h;
    out[(size_t)l*32768 + 16384 + n*128 + k] = lo;
}
__global__ void pack_w256(const float* __restrict__ W, u16* __restrict__ out) {
    int l = blockIdx.y;
    int idx = blockIdx.x*256 + threadIdx.x;
    int kg = idx >> 7, n = idx & 127;
    int half = kg >> 7, kl = kg & 127;
    u16 h, lo; splitf(W[(size_t)l*32768 + idx], h, lo);
    out[(size_t)l*65536 + half*32768 + n*128 + kl] = h;
    out[(size_t)l*65536 + half*32768 + 16384 + n*128 + kl] = lo;
}

// ---------------- counts / CSR build ----------------
__global__ void zero_all_kernel() {
    int i = blockIdx.x*blockDim.x + threadIdx.x;
    g_xagg[i] = 0.f;
    if (i < NN) g_cnt[i] = 0;
    if (i < 2*HH) g_stats[i] = 0.f;
}
__global__ void count_kernel(const int* __restrict__ nodes) {
    int i = blockIdx.x*blockDim.x + threadIdx.x;
    if (i < MROWS) atomicAdd(&g_cnt[nodes[i]], 1);
}
__global__ void inv_kernel() {
    int i = blockIdx.x*blockDim.x + threadIdx.x;
    if (i < NN) g_inv[i] = 1.f / (float)max(g_cnt[i], 1);
}
__global__ void pack_xagg_kernel() {
    int idx = blockIdx.x*256 + threadIdx.x;
    int row = idx >> 7;
    float v = g_xagg[idx] * g_inv[row];
    u16 h, l; splitf(v, h, l);
    g_xah[idx] = h; g_xal[idx] = l;
    g_xagg[idx] = 0.f;
    if (blockIdx.x == 0 && threadIdx.x < 2*HH) g_stats[threadIdx.x] = 0.f;
}
// counting-sort edges of one subgraph by dst -> g_esrt + g_rowptr
__global__ void build_csr_kernel(const int* __restrict__ esrc, const int* __restrict__ edst,
                                 const int* __restrict__ eptr) {
    __shared__ int cnt[KK+1];
    __shared__ int pos[KK];
    const int s = blockIdx.x, tid = threadIdx.x;   // 128 threads
    const int e0 = eptr[s], e1 = eptr[s+1];
    if (tid <= KK) cnt[tid] = 0;
    __syncthreads();
    for (int i = e0 + tid; i < e1; i += 128) atomicAdd(&cnt[edst[i] + 1], 1);
    __syncthreads();
    if (tid == 0)
        for (int r = 1; r <= KK; r++) cnt[r] += cnt[r-1];
    __syncthreads();
    if (tid < KK) pos[tid] = cnt[tid];
    if (tid <= KK) g_rowptr[s*(KK+1) + tid] = cnt[tid];
    __syncthreads();
    for (int i = e0 + tid; i < e1; i += 128) {
        int p = atomicAdd(&pos[edst[i]], 1);
        g_esrt[e0 + p] = esrc[i];
    }
}

// ---------------- persistent init GEMM (64-row tiles, 8 warps) ----------------
__global__ void __launch_bounds__(NT, 1)
init_gemm(const float* __restrict__ logp, const int* __restrict__ rootl,
          const int* __restrict__ nodes, float* __restrict__ Cout)
{
    extern __shared__ __align__(16) char sm[];
    const u32 sb = smem_u32(sm);
    const int tid = threadIdx.x, lane = tid & 31, warp = tid >> 5;
    const int wm = warp & 1, wn = warp >> 1;

    loadW(sb, g_Mb, tid);
    loadA64(sb + 2*PL, g_xph, g_xpl, blockIdx.x * 64, nodes, tid);
    CPCOMMIT();

    u32 ar[2], br[2];
    frag_a(lane, wm, ar);
    frag_b(lane, wn, br);
    const int gid = lane >> 2, tig = lane & 3;

    int j = 0;
    for (int t = blockIdx.x; t < MROWS/64; t += NSM, j++) {
        int tn = t + NSM;
        if (tn < MROWS/64) {
            loadA64(sb + 2*PL + ((j+1)&1)*PL, g_xph, g_xpl, tn*64, nodes, tid);
            CPCOMMIT();
            CPWAIT(1);
        } else {
            CPWAIT(0);
        }
        __syncthreads();

        float c[2][4][4]; ZERO_C24(c);
        gemm64w8(sb + 2*PL + (j&1)*PL, sb, ar, br, c);

        int brow = t * 64;
        #pragma unroll
        for (int mf = 0; mf < 2; mf++) {
            #pragma unroll
            for (int half = 0; half < 2; half++) {
                int gr = brow + wm*32 + mf*16 + half*8 + gid;
                int sub = gr >> 6;
                float lp = logp[sub];
                int isr = ((gr & 63) == rootl[sub]) ? 1 : 0;
                #pragma unroll
                for (int nf = 0; nf < 4; nf++) {
                    int n0 = wn*32 + nf*8 + tig*2;
                    float v0 = c[mf][nf][half*2+0] + g_bias0[n0]
                             + lp * g_vlogp[n0]   + g_root[isr*HH + n0];
                    float v1 = c[mf][nf][half*2+1] + g_bias0[n0+1]
                             + lp * g_vlogp[n0+1] + g_root[isr*HH + n0+1];
                    float2 o; o.x = v0; o.y = v1;
                    *(float2*)(Cout + (size_t)gr*HH + n0) = o;
                }
            }
        }
        __syncthreads();
    }
}

// ---------------- persistent fused layer kernel (64-row tiles, 8 warps) ----------------
__global__ void __launch_bounds__(NT, 1)
layer12_kernel(const u16* __restrict__ w1b, const u16* __restrict__ w2b,
               const float* __restrict__ b1, const float* __restrict__ b2,
               const int* __restrict__ aidx)
{
    extern __shared__ __align__(16) char sm[];
    const u32 sb = smem_u32(sm);
    const int tid = threadIdx.x, lane = tid & 31, warp = tid >> 5;
    const int wm = warp & 1, wn = warp >> 1;
    const int barid = 1 + wm;            // wm-group named barrier (128 threads each)

    loadW(sb, w1b, tid);
    loadW(sb + 2*PL, w2b, tid);
    loadA64(sb + 4*PL, g_zph, g_zpl, blockIdx.x * 64, nullptr, tid);
    CPCOMMIT();

    u32 ar[2], br[2];
    frag_a(lane, wm, ar);
    frag_b(lane, wn, br);
    const int gid = lane >> 2, tig = lane & 3;

    int j = 0;
    for (int t = blockIdx.x; t < MROWS/64; t += NSM, j++) {
        int tn = t + NSM;
        if (tn < MROWS/64) {
            loadA64(sb + 4*PL + ((j+1)&1)*PL, g_zph, g_zpl, tn*64, nullptr, tid);
            CPCOMMIT();
            CPWAIT(1);
        } else {
            CPWAIT(0);
        }
        __syncthreads();

        const u32 aslot = sb + 4*PL + (j&1)*PL;
        float c[2][4][4]; ZERO_C24(c);
        gemm64w8(aslot, sb, ar, br, c);     // z @ W1
        BARG(barid);                         // own wm-row-group reads done

        char* aptr = sm + (4*PL + (j&1)*PL);
        #pragma unroll
        for (int mf = 0; mf < 2; mf++) {
            #pragma unroll
            for (int half = 0; half < 2; half++) {
                int m = wm*32 + mf*16 + half*8 + gid;
                #pragma unroll
                for (int nf = 0; nf < 4; nf++) {
                    int n0 = wn*32 + nf*8 + tig*2;
                    float v0 = fmaxf(c[mf][nf][half*2+0] + b1[n0],   0.f);
                    float v1 = fmaxf(c[mf][nf][half*2+1] + b1[n0+1], 0.f);
                    u32 hi, lo; pack2(v0, v1, hi, lo);
                    u32 off = m*272 + n0*2;
                    *(u32*)(aptr + off)         = hi;
                    *(u32*)(aptr + APL64 + off) = lo;
                }
            }
        }
        BARG(barid);                         // own wm-row-group t-writes visible

        ZERO_C24(c);
        gemm64w8(aslot, sb + 2*PL, ar, br, c);   // t @ W2

        int brow = t * 64;
        #pragma unroll
        for (int mf = 0; mf < 2; mf++) {
            #pragma unroll
            for (int half = 0; half < 2; half++) {
                int gr = brow + wm*32 + mf*16 + half*8 + gid;
                int nd = aidx[gr];
                #pragma unroll
                for (int nf = 0; nf < 4; nf++) {
                    int n0 = wn*32 + nf*8 + tig*2;
                    float v0 = c[mf][nf][half*2+0] + b2[n0];
                    float v1 = c[mf][nf][half*2+1] + b2[n0+1];
                    u32 hi, lo; pack2(v0, v1, hi, lo);
                    *(u32*)(g_z2h + (size_t)gr*HH + n0) = hi;
                    *(u32*)(g_z2l + (size_t)gr*HH + n0) = lo;
                    atomicAdd(&g_xagg[(size_t)nd*HH + n0],     v0);
                    atomicAdd(&g_xagg[(size_t)nd*HH + n0 + 1], v1);
                }
            }
        }
        __syncthreads();                     // protect slots before next cp.async
    }
}

// ---------------- persistent mp2 kernel (64-row tiles, 8 warps, K=256) ----------------
__global__ void __launch_bounds__(NT, 1)
mp2_kernel(const u16* __restrict__ blob, const float* __restrict__ bias,
           const int* __restrict__ aidx, float* __restrict__ uout)
{
    extern __shared__ __align__(16) char sm[];
    const u32 sb = smem_u32(sm);
    const int tid = threadIdx.x, lane = tid & 31, warp = tid >> 5;
    const int wm = warp & 1, wn = warp >> 1;

    loadW(sb, blob, tid);
    loadW(sb + 2*PL, blob + 32768, tid);
    loadA64(sb + 4*PL, g_z2h, g_z2l, blockIdx.x * 64, nullptr, tid);
    CPCOMMIT();

    u32 ar[2], br[2];
    frag_a(lane, wm, ar);
    frag_b(lane, wn, br);
    const int gid = lane >> 2, tig = lane & 3;

    float s0[4], s1[4], q0[4], q1[4];
    #pragma unroll
    for (int nf = 0; nf < 4; nf++) { s0[nf]=0.f; s1[nf]=0.f; q0[nf]=0.f; q1[nf]=0.f; }

    for (int t = blockIdx.x; t < MROWS/64; t += NSM) {
        loadA64(sb + 5*PL, g_xah, g_xal, t*64, aidx, tid);
        CPCOMMIT();
        CPWAIT(1);
        __syncthreads();

        float c[2][4][4]; ZERO_C24(c);
        gemm64w8(sb + 4*PL, sb, ar, br, c);
        __syncthreads();

        int tn = t + NSM;
        if (tn < MROWS/64) {
            loadA64(sb + 4*PL, g_z2h, g_z2l, tn*64, nullptr, tid);
            CPCOMMIT();
            CPWAIT(1);
        } else {
            CPWAIT(0);
        }
        __syncthreads();

        gemm64w8(sb + 5*PL, sb + 2*PL, ar, br, c);

        int brow = t * 64;
        #pragma unroll
        for (int mf = 0; mf < 2; mf++) {
            #pragma unroll
            for (int half = 0; half < 2; half++) {
                int gr = brow + wm*32 + mf*16 + half*8 + gid;
                #pragma unroll
                for (int nf = 0; nf < 4; nf++) {
                    int n0 = wn*32 + nf*8 + tig*2;
                    float v0 = fmaxf(c[mf][nf][half*2+0] + bias[n0],   0.f);
                    float v1 = fmaxf(c[mf][nf][half*2+1] + bias[n0+1], 0.f);
                    float2 o; o.x = v0; o.y = v1;
                    *(float2*)(uout + (size_t)gr*HH + n0) = o;
                    s0[nf] += v0; s1[nf] += v1;
                    q0[nf] += v0*v0; q1[nf] += v1*v1;
                }
            }
        }
        __syncthreads();
    }

    #pragma unroll
    for (int nf = 0; nf < 4; nf++) {
        #pragma unroll
        for (int off = 4; off < 32; off <<= 1) {
            s0[nf] += __shfl_xor_sync(0xFFFFFFFFu, s0[nf], off);
            s1[nf] += __shfl_xor_sync(0xFFFFFFFFu, s1[nf], off);
            q0[nf] += __shfl_xor_sync(0xFFFFFFFFu, q0[nf], off);
            q1[nf] += __shfl_xor_sync(0xFFFFFFFFu, q1[nf], off);
        }
    }
    if (gid == 0) {
        #pragma unroll
        for (int nf = 0; nf < 4; nf++) {
            int n0 = wn*32 + nf*8 + tig*2;
            atomicAdd(&g_stats[n0],      s0[nf]);
            atomicAdd(&g_stats[n0+1],    s1[nf]);
            atomicAdd(&g_stats[HH+n0],   q0[nf]);
            atomicAdd(&g_stats[HH+n0+1], q1[nf]);
        }
    }
}

// ---------------- agg via CSR: register accumulation per row ----------------
// FUSE_BN==0: h = H; FUSE_BN==1: h = bn(u)+H, writes H back.
template<int FUSE_BN>
__global__ void __launch_bounds__(256)
agg_kernel(const float* __restrict__ u, float* __restrict__ H,
           u16* __restrict__ zph, u16* __restrict__ zpl,
           const int* __restrict__ eptr, const float* __restrict__ geps,
           const float* __restrict__ gamma, const float* __restrict__ beta,
           int l)
{
    extern __shared__ float fsm[];
    float* hsm = fsm;                       // [KK][HH] = 32KB
    __shared__ int ssrc[1024];
    __shared__ int rp[KK+1];
    const int s = blockIdx.x;
    const int tid = threadIdx.x;            // 256
    const int grp = tid >> 7, col = tid & 127;
    const float eps1 = 1.f + geps[l];
    const size_t base = (size_t)s * KK;

    float g = 0.f, bt = 0.f, mu = 0.f;
    if (FUSE_BN) {
        const float invM = 1.f / (float)MROWS;
        mu = g_stats[col] * invM;
        float var = g_stats[HH + col] * invM - mu*mu;
        g = gamma[col] * rsqrtf(var + 1e-5f);
        bt = beta[col];
    }

    // rows grp*32 .. grp*32+31 -> hsm
    #pragma unroll 4
    for (int r = grp*32; r < grp*32 + 32; r++) {
        float hv;
        if (FUSE_BN) {
            float uv = u[(base + r)*HH + col];
            hv = (uv - mu) * g + bt + H[(base + r)*HH + col];
            H[(base + r)*HH + col] = hv;
        } else {
            hv = H[(base + r)*HH + col];
        }
        hsm[r*HH + col] = hv;
    }
    // cache CSR
    const int e0 = eptr[s], e1 = eptr[s+1];
    const int etot = e1 - e0;
    for (int i = tid; i < etot && i < 1024; i += 256) ssrc[i] = g_esrt[e0 + i];
    if (tid <= KK) rp[tid] = g_rowptr[s*(KK+1) + tid];
    __syncthreads();

    // per-row register accumulation (all 128 col-threads walk the same edges)
    const bool cached = (etot <= 1024);
    for (int r = grp*32; r < grp*32 + 32; r++) {
        float acc = eps1 * hsm[r*HH + col];
        int a = rp[r], b = rp[r+1];
        if (cached) {
            for (int i = a; i < b; i++)
                acc += hsm[ssrc[i]*HH + col];
        } else {
            for (int i = a; i < b; i++)
                acc += hsm[g_esrt[e0 + i]*HH + col];
        }
        u16 h, lo; splitf(acc, h, lo);
        zph[(base + r)*HH + col] = h;
        zpl[(base + r)*HH + col] = lo;
    }
}

// ---------------- final batchnorm apply ----------------
__global__ void bn_apply_kernel(const float* __restrict__ u, float* __restrict__ h,
                                const float* __restrict__ gamma, const float* __restrict__ beta) {
    int idx = blockIdx.x*blockDim.x + threadIdx.x;
    int c = idx & 127;
    const float invM = 1.f / (float)MROWS;
    float mu  = g_stats[c] * invM;
    float var = g_stats[HH + c] * invM - mu*mu;
    float g = gamma[c] * rsqrtf(var + 1e-5f);
    h[idx] = (u[idx] - mu) * g + beta[c] + h[idx];
}

// ---------------- launch ----------------
extern "C" void kernel_launch(void* const* d_in, const int* in_sizes, int n_in,
                              void* d_out, int out_size) {
    const float* x    = (const float*)d_in[0];
    const float* logp = (const float*)d_in[1];
    const float* npw  = (const float*)d_in[2];
    const float* npb  = (const float*)d_in[3];
    const float* lpw  = (const float*)d_in[4];
    const float* lpb  = (const float*)d_in[5];
    const float* remb = (const float*)d_in[6];
    const float* ipw  = (const float*)d_in[7];
    const float* ipb  = (const float*)d_in[8];
    const float* geps = (const float*)d_in[9];
    const float* w1   = (const float*)d_in[10];
    const float* b1   = (const float*)d_in[11];
    const float* w2   = (const float*)d_in[12];
    const float* b2   = (const float*)d_in[13];
    const float* mp2w = (const float*)d_in[14];
    const float* mp2b = (const float*)d_in[15];
    const float* bng  = (const float*)d_in[16];
    const float* bnb  = (const float*)d_in[17];
    const int* nodes  = (const int*)d_in[18];
    const int* rootl  = (const int*)d_in[19];
    const int* eidx   = (const int*)d_in[20];
    const int* eptr   = (const int*)d_in[21];
    float* hout = (float*)d_out;

    float *p_u;
    u16 *p_zph, *p_zpl, *p_w1b, *p_w2b, *p_mp2b;
    cudaGetSymbolAddress((void**)&p_u, g_u);
    cudaGetSymbolAddress((void**)&p_zph, g_zph);
    cudaGetSymbolAddress((void**)&p_zpl, g_zpl);
    cudaGetSymbolAddress((void**)&p_w1b, g_w1b);
    cudaGetSymbolAddress((void**)&p_w2b, g_w2b);
    cudaGetSymbolAddress((void**)&p_mp2b, g_mp2b);

    const int SM_INIT = 4*PL;             // 139264
    const int SM_BIG  = 6*PL;             // 208896
    const int SMA = KK*HH*4;              // 32768 (hsm only)
    cudaFuncSetAttribute(init_gemm,      cudaFuncAttributeMaxDynamicSharedMemorySize, SM_INIT);
    cudaFuncSetAttribute(layer12_kernel, cudaFuncAttributeMaxDynamicSharedMemorySize, SM_BIG);
    cudaFuncSetAttribute(mp2_kernel,     cudaFuncAttributeMaxDynamicSharedMemorySize, SM_BIG);
    cudaFuncSetAttribute(agg_kernel<0>,  cudaFuncAttributeMaxDynamicSharedMemorySize, SMA);
    cudaFuncSetAttribute(agg_kernel<1>,  cudaFuncAttributeMaxDynamicSharedMemorySize, SMA);

    const int* esrc = eidx;
    const int* edst = eidx + EE;

    // ---- prologue (init_gemm is launch #4 -> captured by ncu) ----
    pack_x_kernel<<<(NN*HH)/256, 256>>>(x);                       // 1
    fold_M_kernel<<<128, 128>>>(npw, ipw);                        // 2
    fold_vec_kernel<<<1, 128>>>(lpw, npb, lpb, remb, ipw, ipb);   // 3
    init_gemm<<<NSM, NT, SM_INIT>>>(logp, rootl, nodes, hout);    // 4 <- profiled
    pack_w12<<<dim3(64, LL, 2), 256>>>(w1, w2);                   // 5
    pack_w256<<<dim3(128, LL), 256>>>(mp2w, p_mp2b);              // 6
    zero_all_kernel<<<(NN*HH)/256, 256>>>();                      // 7
    count_kernel<<<MROWS/256, 256>>>(nodes);                      // 8
    inv_kernel<<<(NN + 255)/256, 256>>>();                        // 9
    build_csr_kernel<<<SS, 128>>>(esrc, edst, eptr);              // 10

    // ---- layers ----
    for (int l = 0; l < LL; l++) {
        if (l == 0)
            agg_kernel<0><<<SS, 256, SMA>>>(nullptr, hout, p_zph, p_zpl,
                                            eptr, geps, nullptr, nullptr, l);
        else
            agg_kernel<1><<<SS, 256, SMA>>>(p_u, hout, p_zph, p_zpl,
                                            eptr, geps, bng + (l-1)*HH, bnb + (l-1)*HH, l);

        layer12_kernel<<<NSM, NT, SM_BIG>>>(p_w1b + (size_t)l*32768,
                                            p_w2b + (size_t)l*32768,
                                            b1 + l*HH, b2 + l*HH, nodes);

        pack_xagg_kernel<<<(NN*HH)/256, 256>>>();

        mp2_kernel<<<NSM, NT, SM_BIG>>>(p_mp2b + (size_t)l*65536,
                                        mp2b + l*HH, nodes, p_u);
    }

    // ---- final BN apply ----
    bn_apply_kernel<<<(MROWS*HH)/256, 256>>>(p_u, hout, bng + (LL-1)*HH, bnb + (LL-1)*HH);
}

// round 15
// speedup vs baseline: 1.2042x; 1.0196x over previous
#include <cuda_runtime.h>
#include <cuda_bf16.h>

#define NN     50000
#define SS     2048
#define KK     64
#define HH     128
#define EE     524288
#define LL     5
#define MROWS  (SS*KK)      // 131072
#define PL     34816        // full smem plane: 128 rows x 272B
#define APL64  17408        // 64-row plane
#define NSM    148
#define NT     512          // 16 warps, warp tile 16m x 32n

typedef unsigned short u16;
typedef unsigned int   u32;

// ---------------- scratch (device globals; no allocations) ----------------
__device__ u16 g_Mb[2*16384];
__device__ u16 g_w1b[LL*2*16384];
__device__ u16 g_w2b[LL*2*16384];
__device__ u16 g_mp2b[LL*4*16384];
__device__ float g_vlogp[HH];
__device__ float g_bias0[HH];
__device__ float g_root[2*HH];
__device__ u16 g_xph[NN*HH],    g_xpl[NN*HH];
__device__ u16 g_zph[MROWS*HH], g_zpl[MROWS*HH];
__device__ u16 g_z2h[MROWS*HH], g_z2l[MROWS*HH];
__device__ u16 g_xah[NN*HH],    g_xal[NN*HH];
__device__ float g_u[MROWS*HH];
__device__ float g_xagg[NN*HH];
__device__ float g_inv[NN];
__device__ int   g_cnt[NN];
__device__ float g_stats[2*HH];
__device__ int   g_esrt[EE];             // edge sources, sorted by dst per subgraph
__device__ int   g_rowptr[SS*(KK+1)];    // per-subgraph CSR row pointers

// ---------------- helpers ----------------
__device__ __forceinline__ void splitf(float v, u16& h, u16& l) {
    __nv_bfloat16 hb = __float2bfloat16_rn(v);
    __nv_bfloat16 lb = __float2bfloat16_rn(v - __bfloat162float(hb));
    h = __bfloat16_as_ushort(hb);
    l = __bfloat16_as_ushort(lb);
}
__device__ __forceinline__ void pack2(float v0, float v1, u32& hi, u32& lo) {
    u16 h0, l0, h1, l1;
    splitf(v0, h0, l0); splitf(v1, h1, l1);
    hi = (u32)h0 | ((u32)h1 << 16);
    lo = (u32)l0 | ((u32)l1 << 16);
}
__device__ __forceinline__ u32 smem_u32(const void* p) {
    u32 a;
    asm("{ .reg .u64 t; cvta.to.shared.u64 t, %1; cvt.u32.u64 %0, t; }" : "=r"(a) : "l"(p));
    return a;
}

#define CP16(dst, src) \
    asm volatile("cp.async.cg.shared.global [%0], [%1], 16;" :: "r"(dst), "l"(src) : "memory")
#define CPCOMMIT() asm volatile("cp.async.commit_group;" ::: "memory")
#define CPWAIT(n)  asm volatile("cp.async.wait_group %0;" :: "n"(n) : "memory")
#define BARG(id)   asm volatile("bar.sync %0, 128;" :: "r"(id) : "memory")

#define LDSM4(R0,R1,R2,R3,ADDR) \
    asm volatile("ldmatrix.sync.aligned.m8n8.x4.shared.b16 {%0,%1,%2,%3}, [%4];" \
        : "=r"(R0),"=r"(R1),"=r"(R2),"=r"(R3) : "r"(ADDR))

#define MMA_BF16(C, A0,A1,A2,A3, B0,B1) \
    asm volatile("mma.sync.aligned.m16n8k16.row.col.f32.bf16.bf16.f32 " \
        "{%0,%1,%2,%3},{%4,%5,%6,%7},{%8,%9},{%0,%1,%2,%3};" \
        : "+f"(C[0]),"+f"(C[1]),"+f"(C[2]),"+f"(C[3]) \
        : "r"(A0),"r"(A1),"r"(A2),"r"(A3),"r"(B0),"r"(B1))

// ---- 64-row 3-term core, 16-warp layout (warp tile 16m x 32n) ----
// A slot: hi@aB, lo@aB+APL64. B planes: hi@bB, lo@bB+PL.
__device__ __forceinline__ void gemm64w16(u32 aB, u32 bB,
                                          u32 ar, const u32* br, float c[4][4])
{
    #pragma unroll
    for (int ks = 0; ks < 8; ks++) {
        const u32 ko = ks*32;
        unsigned ah[4], al[4], bh[2][4], bl[2][4];
        LDSM4(ah[0],ah[1],ah[2],ah[3], aB + ar + ko);
        LDSM4(al[0],al[1],al[2],al[3], aB + APL64 + ar + ko);
        LDSM4(bh[0][0],bh[0][1],bh[0][2],bh[0][3], bB + br[0] + ko);
        LDSM4(bh[1][0],bh[1][1],bh[1][2],bh[1][3], bB + br[1] + ko);
        #pragma unroll
        for (int g = 0; g < 2; g++) {
            MMA_BF16(c[2*g+0], ah[0],ah[1],ah[2],ah[3], bh[g][0],bh[g][2]);
            MMA_BF16(c[2*g+1], ah[0],ah[1],ah[2],ah[3], bh[g][1],bh[g][3]);
        }
        LDSM4(bl[0][0],bl[0][1],bl[0][2],bl[0][3], bB + PL + br[0] + ko);
        LDSM4(bl[1][0],bl[1][1],bl[1][2],bl[1][3], bB + PL + br[1] + ko);
        #pragma unroll
        for (int g = 0; g < 2; g++) {
            MMA_BF16(c[2*g+0], al[0],al[1],al[2],al[3], bh[g][0],bh[g][2]);
            MMA_BF16(c[2*g+1], al[0],al[1],al[2],al[3], bh[g][1],bh[g][3]);
        }
        #pragma unroll
        for (int g = 0; g < 2; g++) {
            MMA_BF16(c[2*g+0], ah[0],ah[1],ah[2],ah[3], bl[g][0],bl[g][2]);
            MMA_BF16(c[2*g+1], ah[0],ah[1],ah[2],ah[3], bl[g][1],bl[g][3]);
        }
    }
}

#define ZERO_C4(c) { _Pragma("unroll") for (int j=0;j<4;j++) \
    _Pragma("unroll") for (int q=0;q<4;q++) (c)[j][q]=0.f; }

__device__ __forceinline__ void frag_b(int lane, int wn, u32* br) {
    #pragma unroll
    for (int g = 0; g < 2; g++) {
        int row = wn*32 + g*16 + ((lane>>3)&1)*8 + (lane&7);
        br[g] = row*272 + (lane>>4)*16;
    }
}

// ---- smem loaders (512 threads; caller commits) ----
__device__ __forceinline__ void loadW(u32 dst, const u16* blob, int tid) {
    #pragma unroll
    for (int it = 0; it < 8; it++) {
        int ch = tid + it*NT;                  // 4096 chunks
        int pl = ch >> 11, rem = ch & 2047, r = rem >> 4, q = rem & 15;
        CP16(dst + pl*PL + r*272 + q*16, blob + (size_t)pl*16384 + r*128 + q*8);
    }
}
__device__ __forceinline__ void loadA64(u32 dst, const u16* Ah, const u16* Al,
                                        int rowbase, const int* idx, int tid) {
    #pragma unroll
    for (int it = 0; it < 4; it++) {
        int ch = tid + it*NT;                  // 2048 chunks
        int pl = ch >> 10, rem = ch & 1023, r = rem >> 4, q = rem & 15;
        int row = idx ? idx[rowbase + r] : (rowbase + r);
        CP16(dst + pl*APL64 + r*272 + q*16, (pl ? Al : Ah) + (size_t)row*HH + q*8);
    }
}

// ---------------- packing kernels ----------------
__global__ void pack_x_kernel(const float* __restrict__ x) {
    int idx = blockIdx.x*256 + threadIdx.x;
    u16 h, l; splitf(x[idx], h, l);
    g_xph[idx] = h; g_xpl[idx] = l;
}
__global__ void fold_M_kernel(const float* __restrict__ npw, const float* __restrict__ ipw) {
    int k = blockIdx.x, n = threadIdx.x;
    float s = 0.f;
    for (int c = 0; c < HH; c++) s += npw[k*HH + c] * ipw[c*HH + n];
    u16 h, l; splitf(s, h, l);
    g_Mb[n*128 + k] = h; g_Mb[16384 + n*128 + k] = l;
}
__global__ void fold_vec_kernel(const float* __restrict__ lpw, const float* __restrict__ npb,
                                const float* __restrict__ lpb, const float* __restrict__ remb,
                                const float* __restrict__ ipw, const float* __restrict__ ipb) {
    int j = threadIdx.x;
    float v = 0.f, b = ipb[j], r0 = 0.f, r1 = 0.f;
    for (int k = 0; k < HH; k++) {
        float wa = ipw[k*HH + j];
        float wb = ipw[(HH + k)*HH + j];
        float wc = ipw[(2*HH + k)*HH + j];
        v  += lpw[k] * wb;
        b  += npb[k] * wa + lpb[k] * wb;
        r0 += remb[k] * wc;
        r1 += remb[HH + k] * wc;
    }
    g_vlogp[j] = v; g_bias0[j] = b; g_root[j] = r0; g_root[HH + j] = r1;
}
__global__ void pack_w12(const float* __restrict__ W1, const float* __restrict__ W2) {
    int l = blockIdx.y;
    int idx = blockIdx.x*256 + threadIdx.x;
    int k = idx >> 7, n = idx & 127;
    const float* W = blockIdx.z ? W2 : W1;
    u16* out = blockIdx.z ? g_w2b : g_w1b;
    u16 h, lo; splitf(W[(size_t)l*16384 + idx], h, lo);
    out[(size_t)l*32768 + n*128 + k] = h;
    out[(size_t)l*32768 + 16384 + n*128 + k] = lo;
}
__global__ void pack_w256(const float* __restrict__ W, u16* __restrict__ out) {
    int l = blockIdx.y;
    int idx = blockIdx.x*256 + threadIdx.x;
    int kg = idx >> 7, n = idx & 127;
    int half = kg >> 7, kl = kg & 127;
    u16 h, lo; splitf(W[(size_t)l*32768 + idx], h, lo);
    out[(size_t)l*65536 + half*32768 + n*128 + kl] = h;
    out[(size_t)l*65536 + half*32768 + 16384 + n*128 + kl] = lo;
}

// ---------------- counts / CSR build ----------------
__global__ void zero_all_kernel() {
    int i = blockIdx.x*blockDim.x + threadIdx.x;
    g_xagg[i] = 0.f;
    if (i < NN) g_cnt[i] = 0;
    if (i < 2*HH) g_stats[i] = 0.f;
}
__global__ void count_kernel(const int* __restrict__ nodes) {
    int i = blockIdx.x*blockDim.x + threadIdx.x;
    if (i < MROWS) atomicAdd(&g_cnt[nodes[i]], 1);
}
__global__ void inv_kernel() {
    int i = blockIdx.x*blockDim.x + threadIdx.x;
    if (i < NN) g_inv[i] = 1.f / (float)max(g_cnt[i], 1);
}
__global__ void pack_xagg_kernel() {
    int idx = blockIdx.x*256 + threadIdx.x;
    int row = idx >> 7;
    float v = g_xagg[idx] * g_inv[row];
    u16 h, l; splitf(v, h, l);
    g_xah[idx] = h; g_xal[idx] = l;
    g_xagg[idx] = 0.f;
    if (blockIdx.x == 0 && threadIdx.x < 2*HH) g_stats[threadIdx.x] = 0.f;
}
__global__ void build_csr_kernel(const int* __restrict__ esrc, const int* __restrict__ edst,
                                 const int* __restrict__ eptr) {
    __shared__ int cnt[KK+1];
    __shared__ int pos[KK];
    const int s = blockIdx.x, tid = threadIdx.x;   // 128 threads
    const int e0 = eptr[s], e1 = eptr[s+1];
    if (tid <= KK) cnt[tid] = 0;
    __syncthreads();
    for (int i = e0 + tid; i < e1; i += 128) atomicAdd(&cnt[edst[i] + 1], 1);
    __syncthreads();
    if (tid == 0)
        for (int r = 1; r <= KK; r++) cnt[r] += cnt[r-1];
    __syncthreads();
    if (tid < KK) pos[tid] = cnt[tid];
    if (tid <= KK) g_rowptr[s*(KK+1) + tid] = cnt[tid];
    __syncthreads();
    for (int i = e0 + tid; i < e1; i += 128) {
        int p = atomicAdd(&pos[edst[i]], 1);
        g_esrt[e0 + p] = esrc[i];
    }
}

// ---------------- persistent init GEMM (64-row tiles, 16 warps, triple-buffer) ----------------
__global__ void __launch_bounds__(NT, 1)
init_gemm(const float* __restrict__ logp, const int* __restrict__ rootl,
          const int* __restrict__ nodes, float* __restrict__ Cout)
{
    extern __shared__ __align__(16) char sm[];
    const u32 sb = smem_u32(sm);          // M planes [0,2PL); A slots 2PL + s*PL (3 slots)
    const int tid = threadIdx.x, lane = tid & 31, warp = tid >> 5;
    const int wm = warp & 3, wn = warp >> 2;

    loadW(sb, g_Mb, tid);
    loadA64(sb + 2*PL, g_xph, g_xpl, blockIdx.x * 64, nodes, tid);
    CPCOMMIT();

    const u32 ar = (wm*16 + (lane & 15))*272 + (lane>>4)*16;
    u32 br[2]; frag_b(lane, wn, br);
    const int gid = lane >> 2, tig = lane & 3;

    int j = 0;
    for (int t = blockIdx.x; t < MROWS/64; t += NSM, j++) {
        int tn = t + NSM;
        if (tn < MROWS/64) {
            int sn = (j+1) % 3;
            loadA64(sb + 2*PL + sn*PL, g_xph, g_xpl, tn*64, nodes, tid);
            CPCOMMIT();
            CPWAIT(1);
        } else {
            CPWAIT(0);
        }
        __syncthreads();

        float c[4][4]; ZERO_C4(c);
        gemm64w16(sb + 2*PL + (j%3)*PL, sb, ar, br, c);

        int brow = t * 64;
        #pragma unroll
        for (int half = 0; half < 2; half++) {
            int gr = brow + wm*16 + half*8 + gid;
            int sub = gr >> 6;
            float lp = logp[sub];
            int isr = ((gr & 63) == rootl[sub]) ? 1 : 0;
            #pragma unroll
            for (int nf = 0; nf < 4; nf++) {
                int n0 = wn*32 + nf*8 + tig*2;
                float v0 = c[nf][half*2+0] + g_bias0[n0]
                         + lp * g_vlogp[n0]   + g_root[isr*HH + n0];
                float v1 = c[nf][half*2+1] + g_bias0[n0+1]
                         + lp * g_vlogp[n0+1] + g_root[isr*HH + n0+1];
                float2 o; o.x = v0; o.y = v1;
                *(float2*)(Cout + (size_t)gr*HH + n0) = o;
            }
        }
        // no trailing sync: 3-slot reuse distance + top-of-loop sync bound drift
    }
}

// ---------------- persistent fused layer kernel (64-row tiles, 16 warps) ----------------
__global__ void __launch_bounds__(NT, 1)
layer12_kernel(const u16* __restrict__ w1b, const u16* __restrict__ w2b,
               const float* __restrict__ b1, const float* __restrict__ b2,
               const int* __restrict__ aidx)
{
    extern __shared__ __align__(16) char sm[];
    const u32 sb = smem_u32(sm);          // W1 [0,2PL); W2 [2PL,4PL); A slots 4PL + s*PL
    const int tid = threadIdx.x, lane = tid & 31, warp = tid >> 5;
    const int wm = warp & 3, wn = warp >> 2;
    const int barid = 1 + wm;            // 4 wm-groups x 128 threads

    loadW(sb, w1b, tid);
    loadW(sb + 2*PL, w2b, tid);
    loadA64(sb + 4*PL, g_zph, g_zpl, blockIdx.x * 64, nullptr, tid);
    CPCOMMIT();

    const u32 ar = (wm*16 + (lane & 15))*272 + (lane>>4)*16;
    u32 br[2]; frag_b(lane, wn, br);
    const int gid = lane >> 2, tig = lane & 3;

    int j = 0;
    for (int t = blockIdx.x; t < MROWS/64; t += NSM, j++) {
        int tn = t + NSM;
        if (tn < MROWS/64) {
            loadA64(sb + 4*PL + ((j+1)&1)*PL, g_zph, g_zpl, tn*64, nullptr, tid);
            CPCOMMIT();
            CPWAIT(1);
        } else {
            CPWAIT(0);
        }
        __syncthreads();

        const u32 aslot = sb + 4*PL + (j&1)*PL;
        float c[4][4]; ZERO_C4(c);
        gemm64w16(aslot, sb, ar, br, c);    // z @ W1
        BARG(barid);                         // own wm-row-group reads done

        char* aptr = sm + (4*PL + (j&1)*PL);
        #pragma unroll
        for (int half = 0; half < 2; half++) {
            int m = wm*16 + half*8 + gid;
            #pragma unroll
            for (int nf = 0; nf < 4; nf++) {
                int n0 = wn*32 + nf*8 + tig*2;
                float v0 = fmaxf(c[nf][half*2+0] + b1[n0],   0.f);
                float v1 = fmaxf(c[nf][half*2+1] + b1[n0+1], 0.f);
                u32 hi, lo; pack2(v0, v1, hi, lo);
                u32 off = m*272 + n0*2;
                *(u32*)(aptr + off)         = hi;
                *(u32*)(aptr + APL64 + off) = lo;
            }
        }
        BARG(barid);                         // own wm-row-group t-writes visible

        ZERO_C4(c);
        gemm64w16(aslot, sb + 2*PL, ar, br, c);   // t @ W2

        int brow = t * 64;
        #pragma unroll
        for (int half = 0; half < 2; half++) {
            int gr = brow + wm*16 + half*8 + gid;
            int nd = aidx[gr];
            #pragma unroll
            for (int nf = 0; nf < 4; nf++) {
                int n0 = wn*32 + nf*8 + tig*2;
                float v0 = c[nf][half*2+0] + b2[n0];
                float v1 = c[nf][half*2+1] + b2[n0+1];
                u32 hi, lo; pack2(v0, v1, hi, lo);
                *(u32*)(g_z2h + (size_t)gr*HH + n0) = hi;
                *(u32*)(g_z2l + (size_t)gr*HH + n0) = lo;
                atomicAdd(&g_xagg[(size_t)nd*HH + n0],     v0);
                atomicAdd(&g_xagg[(size_t)nd*HH + n0 + 1], v1);
            }
        }
        __syncthreads();                     // protect A slots before next cp.async
    }
}

// ---------------- persistent mp2 kernel (64-row tiles, 16 warps, K=256) ----------------
__global__ void __launch_bounds__(NT, 1)
mp2_kernel(const u16* __restrict__ blob, const float* __restrict__ bias,
           const int* __restrict__ aidx, float* __restrict__ uout)
{
    extern __shared__ __align__(16) char sm[];
    const u32 sb = smem_u32(sm);          // Wh0 [0,2PL); Wh1 [2PL,4PL); slotZ 4PL; slotX 5PL
    const int tid = threadIdx.x, lane = tid & 31, warp = tid >> 5;
    const int wm = warp & 3, wn = warp >> 2;

    loadW(sb, blob, tid);
    loadW(sb + 2*PL, blob + 32768, tid);
    loadA64(sb + 4*PL, g_z2h, g_z2l, blockIdx.x * 64, nullptr, tid);
    CPCOMMIT();

    const u32 ar = (wm*16 + (lane & 15))*272 + (lane>>4)*16;
    u32 br[2]; frag_b(lane, wn, br);
    const int gid = lane >> 2, tig = lane & 3;

    float s0[4], s1[4], q0[4], q1[4];
    #pragma unroll
    for (int nf = 0; nf < 4; nf++) { s0[nf]=0.f; s1[nf]=0.f; q0[nf]=0.f; q1[nf]=0.f; }

    for (int t = blockIdx.x; t < MROWS/64; t += NSM) {
        loadA64(sb + 5*PL, g_xah, g_xal, t*64, aidx, tid);
        CPCOMMIT();
        CPWAIT(1);                       // z2 chunk ready
        __syncthreads();

        float c[4][4]; ZERO_C4(c);
        gemm64w16(sb + 4*PL, sb, ar, br, c);        // z2 @ W[half0]
        __syncthreads();                             // slotZ reads done

        int tn = t + NSM;
        if (tn < MROWS/64) {
            loadA64(sb + 4*PL, g_z2h, g_z2l, tn*64, nullptr, tid);
            CPCOMMIT();
            CPWAIT(1);                  // xa chunk ready
        } else {
            CPWAIT(0);
        }
        __syncthreads();

        gemm64w16(sb + 5*PL, sb + 2*PL, ar, br, c); // += xa @ W[half1]

        int brow = t * 64;
        #pragma unroll
        for (int half = 0; half < 2; half++) {
            int gr = brow + wm*16 + half*8 + gid;
            #pragma unroll
            for (int nf = 0; nf < 4; nf++) {
                int n0 = wn*32 + nf*8 + tig*2;
                float v0 = fmaxf(c[nf][half*2+0] + bias[n0],   0.f);
                float v1 = fmaxf(c[nf][half*2+1] + bias[n0+1], 0.f);
                float2 o; o.x = v0; o.y = v1;
                *(float2*)(uout + (size_t)gr*HH + n0) = o;
                s0[nf] += v0; s1[nf] += v1;
                q0[nf] += v0*v0; q1[nf] += v1*v1;
            }
        }
        __syncthreads();                             // protect slotX for next tile
    }

    #pragma unroll
    for (int nf = 0; nf < 4; nf++) {
        #pragma unroll
        for (int off = 4; off < 32; off <<= 1) {
            s0[nf] += __shfl_xor_sync(0xFFFFFFFFu, s0[nf], off);
            s1[nf] += __shfl_xor_sync(0xFFFFFFFFu, s1[nf], off);
            q0[nf] += __shfl_xor_sync(0xFFFFFFFFu, q0[nf], off);
            q1[nf] += __shfl_xor_sync(0xFFFFFFFFu, q1[nf], off);
        }
    }
    if (gid == 0) {
        #pragma unroll
        for (int nf = 0; nf < 4; nf++) {
            int n0 = wn*32 + nf*8 + tig*2;
            atomicAdd(&g_stats[n0],      s0[nf]);
            atomicAdd(&g_stats[n0+1],    s1[nf]);
            atomicAdd(&g_stats[HH+n0],   q0[nf]);
            atomicAdd(&g_stats[HH+n0+1], q1[nf]);
        }
    }
}

// ---------------- agg via CSR: register accumulation per row ----------------
template<int FUSE_BN>
__global__ void __launch_bounds__(256)
agg_kernel(const float* __restrict__ u, float* __restrict__ H,
           u16* __restrict__ zph, u16* __restrict__ zpl,
           const int* __restrict__ eptr, const float* __restrict__ geps,
           const float* __restrict__ gamma, const float* __restrict__ beta,
           int l)
{
    extern __shared__ float fsm[];
    float* hsm = fsm;                       // [KK][HH] = 32KB
    __shared__ int ssrc[1024];
    __shared__ int rp[KK+1];
    const int s = blockIdx.x;
    const int tid = threadIdx.x;            // 256
    const int grp = tid >> 7, col = tid & 127;
    const float eps1 = 1.f + geps[l];
    const size_t base = (size_t)s * KK;

    float g = 0.f, bt = 0.f, mu = 0.f;
    if (FUSE_BN) {
        const float invM = 1.f / (float)MROWS;
        mu = g_stats[col] * invM;
        float var = g_stats[HH + col] * invM - mu*mu;
        g = gamma[col] * rsqrtf(var + 1e-5f);
        bt = beta[col];
    }

    #pragma unroll 4
    for (int r = grp*32; r < grp*32 + 32; r++) {
        float hv;
        if (FUSE_BN) {
            float uv = u[(base + r)*HH + col];
            hv = (uv - mu) * g + bt + H[(base + r)*HH + col];
            H[(base + r)*HH + col] = hv;
        } else {
            hv = H[(base + r)*HH + col];
        }
        hsm[r*HH + col] = hv;
    }
    const int e0 = eptr[s], e1 = eptr[s+1];
    const int etot = e1 - e0;
    for (int i = tid; i < etot && i < 1024; i += 256) ssrc[i] = g_esrt[e0 + i];
    if (tid <= KK) rp[tid] = g_rowptr[s*(KK+1) + tid];
    __syncthreads();

    const bool cached = (etot <= 1024);
    for (int r = grp*32; r < grp*32 + 32; r++) {
        float acc = eps1 * hsm[r*HH + col];
        int a = rp[r], b = rp[r+1];
        if (cached) {
            for (int i = a; i < b; i++)
                acc += hsm[ssrc[i]*HH + col];
        } else {
            for (int i = a; i < b; i++)
                acc += hsm[g_esrt[e0 + i]*HH + col];
        }
        u16 h, lo; splitf(acc, h, lo);
        zph[(base + r)*HH + col] = h;
        zpl[(base + r)*HH + col] = lo;
    }
}

// ---------------- final batchnorm apply ----------------
__global__ void bn_apply_kernel(const float* __restrict__ u, float* __restrict__ h,
                                const float* __restrict__ gamma, const float* __restrict__ beta) {
    int idx = blockIdx.x*blockDim.x + threadIdx.x;
    int c = idx & 127;
    const float invM = 1.f / (float)MROWS;
    float mu  = g_stats[c] * invM;
    float var = g_stats[HH + c] * invM - mu*mu;
    float g = gamma[c] * rsqrtf(var + 1e-5f);
    h[idx] = (u[idx] - mu) * g + beta[c] + h[idx];
}

// ---------------- launch ----------------
extern "C" void kernel_launch(void* const* d_in, const int* in_sizes, int n_in,
                              void* d_out, int out_size) {
    const float* x    = (const float*)d_in[0];
    const float* logp = (const float*)d_in[1];
    const float* npw  = (const float*)d_in[2];
    const float* npb  = (const float*)d_in[3];
    const float* lpw  = (const float*)d_in[4];
    const float* lpb  = (const float*)d_in[5];
    const float* remb = (const float*)d_in[6];
    const float* ipw  = (const float*)d_in[7];
    const float* ipb  = (const float*)d_in[8];
    const float* geps = (const float*)d_in[9];
    const float* w1   = (const float*)d_in[10];
    const float* b1   = (const float*)d_in[11];
    const float* w2   = (const float*)d_in[12];
    const float* b2   = (const float*)d_in[13];
    const float* mp2w = (const float*)d_in[14];
    const float* mp2b = (const float*)d_in[15];
    const float* bng  = (const float*)d_in[16];
    const float* bnb  = (const float*)d_in[17];
    const int* nodes  = (const int*)d_in[18];
    const int* rootl  = (const int*)d_in[19];
    const int* eidx   = (const int*)d_in[20];
    const int* eptr   = (const int*)d_in[21];
    float* hout = (float*)d_out;

    float *p_u;
    u16 *p_zph, *p_zpl, *p_w1b, *p_w2b, *p_mp2b;
    cudaGetSymbolAddress((void**)&p_u, g_u);
    cudaGetSymbolAddress((void**)&p_zph, g_zph);
    cudaGetSymbolAddress((void**)&p_zpl, g_zpl);
    cudaGetSymbolAddress((void**)&p_w1b, g_w1b);
    cudaGetSymbolAddress((void**)&p_w2b, g_w2b);
    cudaGetSymbolAddress((void**)&p_mp2b, g_mp2b);

    const int SM_INIT = 5*PL;             // 174080 (3 A slots)
    const int SM_BIG  = 6*PL;             // 208896
    const int SMA = KK*HH*4;              // 32768
    cudaFuncSetAttribute(init_gemm,      cudaFuncAttributeMaxDynamicSharedMemorySize, SM_INIT);
    cudaFuncSetAttribute(layer12_kernel, cudaFuncAttributeMaxDynamicSharedMemorySize, SM_BIG);
    cudaFuncSetAttribute(mp2_kernel,     cudaFuncAttributeMaxDynamicSharedMemorySize, SM_BIG);
    cudaFuncSetAttribute(agg_kernel<0>,  cudaFuncAttributeMaxDynamicSharedMemorySize, SMA);
    cudaFuncSetAttribute(agg_kernel<1>,  cudaFuncAttributeMaxDynamicSharedMemorySize, SMA);

    const int* esrc = eidx;
    const int* edst = eidx + EE;

    // ---- prologue (init_gemm is launch #4 -> captured by ncu) ----
    pack_x_kernel<<<(NN*HH)/256, 256>>>(x);                       // 1
    fold_M_kernel<<<128, 128>>>(npw, ipw);                        // 2
    fold_vec_kernel<<<1, 128>>>(lpw, npb, lpb, remb, ipw, ipb);   // 3
    init_gemm<<<NSM, NT, SM_INIT>>>(logp, rootl, nodes, hout);    // 4 <- profiled
    pack_w12<<<dim3(64, LL, 2), 256>>>(w1, w2);                   // 5
    pack_w256<<<dim3(128, LL), 256>>>(mp2w, p_mp2b);              // 6
    zero_all_kernel<<<(NN*HH)/256, 256>>>();                      // 7
    count_kernel<<<MROWS/256, 256>>>(nodes);                      // 8
    inv_kernel<<<(NN + 255)/256, 256>>>();                        // 9
    build_csr_kernel<<<SS, 128>>>(esrc, edst, eptr);              // 10

    // ---- layers ----
    for (int l = 0; l < LL; l++) {
        if (l == 0)
            agg_kernel<0><<<SS, 256, SMA>>>(nullptr, hout, p_zph, p_zpl,
                                            eptr, geps, nullptr, nullptr, l);
        else
            agg_kernel<1><<<SS, 256, SMA>>>(p_u, hout, p_zph, p_zpl,
                                            eptr, geps, bng + (l-1)*HH, bnb + (l-1)*HH, l);

        layer12_kernel<<<NSM, NT, SM_BIG>>>(p_w1b + (size_t)l*32768,
                                            p_w2b + (size_t)l*32768,
                                            b1 + l*HH, b2 + l*HH, nodes);

        pack_xagg_kernel<<<(NN*HH)/256, 256>>>();

        mp2_kernel<<<NSM, NT, SM_BIG>>>(p_mp2b + (size_t)l*65536,
                                        mp2b + l*HH, nodes, p_u);
    }

    // ---- final BN apply ----
    bn_apply_kernel<<<(MROWS*HH)/256, 256>>>(p_u, hout, bng + (LL-1)*HH, bnb + (LL-1)*HH);
}

// round 16
// speedup vs baseline: 1.2440x; 1.0330x over previous
#include <cuda_runtime.h>
#include <cuda_bf16.h>

#define NN     50000
#define SS     2048
#define KK     64
#define HH     128
#define EE     524288
#define LL     5
#define MROWS  (SS*KK)      // 131072
#define PL     34816        // full smem plane: 128 rows x 272B
#define APL64  17408        // 64-row plane
#define NSM    148
#define NT     256          // 8 warps, warp tile 32m x 32n

typedef unsigned short u16;
typedef unsigned int   u32;

// ---------------- scratch (device globals; no allocations) ----------------
__device__ u16 g_Mb[2*16384];
__device__ u16 g_w1b[LL*2*16384];
__device__ u16 g_w2b[LL*2*16384];
__device__ u16 g_mp2b[LL*4*16384];
__device__ float g_vlogp[HH];
__device__ float g_bias0[HH];
__device__ float g_root[2*HH];
__device__ u16 g_xph[NN*HH],    g_xpl[NN*HH];
__device__ u16 g_zph[MROWS*HH], g_zpl[MROWS*HH];
__device__ u16 g_z2h[MROWS*HH], g_z2l[MROWS*HH];
__device__ u16 g_xah[NN*HH],    g_xal[NN*HH];
__device__ float g_u[MROWS*HH];
__device__ float g_xagg[NN*HH];
__device__ float g_inv[NN];
__device__ int   g_cnt[NN];
__device__ float g_stats[2*HH];
__device__ int   g_esrt[EE];
__device__ int   g_rowptr[SS*(KK+1)];

// ---------------- helpers ----------------
__device__ __forceinline__ void splitf(float v, u16& h, u16& l) {
    __nv_bfloat16 hb = __float2bfloat16_rn(v);
    __nv_bfloat16 lb = __float2bfloat16_rn(v - __bfloat162float(hb));
    h = __bfloat16_as_ushort(hb);
    l = __bfloat16_as_ushort(lb);
}
__device__ __forceinline__ void pack2(float v0, float v1, u32& hi, u32& lo) {
    u16 h0, l0, h1, l1;
    splitf(v0, h0, l0); splitf(v1, h1, l1);
    hi = (u32)h0 | ((u32)h1 << 16);
    lo = (u32)l0 | ((u32)l1 << 16);
}
__device__ __forceinline__ u32 smem_u32(const void* p) {
    u32 a;
    asm("{ .reg .u64 t; cvta.to.shared.u64 t, %1; cvt.u32.u64 %0, t; }" : "=r"(a) : "l"(p));
    return a;
}

#define CP16(dst, src) \
    asm volatile("cp.async.cg.shared.global [%0], [%1], 16;" :: "r"(dst), "l"(src) : "memory")
#define CPCOMMIT() asm volatile("cp.async.commit_group;" ::: "memory")
#define CPWAIT(n)  asm volatile("cp.async.wait_group %0;" :: "n"(n) : "memory")
#define BARG(id)   asm volatile("bar.sync %0, 128;" :: "r"(id) : "memory")

#define LDSM4(R0,R1,R2,R3,ADDR) \
    asm volatile("ldmatrix.sync.aligned.m8n8.x4.shared.b16 {%0,%1,%2,%3}, [%4];" \
        : "=r"(R0),"=r"(R1),"=r"(R2),"=r"(R3) : "r"(ADDR))

#define MMA_BF16(C, A0,A1,A2,A3, B0,B1) \
    asm volatile("mma.sync.aligned.m16n8k16.row.col.f32.bf16.bf16.f32 " \
        "{%0,%1,%2,%3},{%4,%5,%6,%7},{%8,%9},{%0,%1,%2,%3};" \
        : "+f"(C[0]),"+f"(C[1]),"+f"(C[2]),"+f"(C[3]) \
        : "r"(A0),"r"(A1),"r"(A2),"r"(A3),"r"(B0),"r"(B1))

#define ZERO_C24(c) { _Pragma("unroll") for (int i=0;i<2;i++) _Pragma("unroll") \
    for (int j=0;j<4;j++) _Pragma("unroll") for (int q=0;q<4;q++) (c)[i][j][q]=0.f; }

__device__ __forceinline__ void frag_a(int lane, int wm, u32* ar) {
    #pragma unroll
    for (int mf = 0; mf < 2; mf++) {
        int row = wm*32 + mf*16 + (lane & 15);
        ar[mf] = row*272 + (lane>>4)*16;
    }
}
__device__ __forceinline__ void frag_b(int lane, int wn, u32* br) {
    #pragma unroll
    for (int g = 0; g < 2; g++) {
        int row = wn*32 + g*16 + ((lane>>3)&1)*8 + (lane&7);
        br[g] = row*272 + (lane>>4)*16;
    }
}

// ---- preload B fragments (both planes) into registers: 128 regs/warp ----
#define PRELOADB(Bh, Bl, bB, br) { \
    _Pragma("unroll") for (int ks = 0; ks < 8; ks++) { \
        _Pragma("unroll") for (int g = 0; g < 2; g++) { \
            LDSM4((Bh)[ks][g][0],(Bh)[ks][g][1],(Bh)[ks][g][2],(Bh)[ks][g][3], \
                  (bB) + (br)[g] + ks*32); \
            LDSM4((Bl)[ks][g][0],(Bl)[ks][g][1],(Bl)[ks][g][2],(Bl)[ks][g][3], \
                  (bB) + PL + (br)[g] + ks*32); \
        } \
    } }

// ---- 64-row 3-term core, register-resident B (4 A-LDSM + 24 MMA per ks) ----
__device__ __forceinline__ void gemm64_rB(u32 aB, const u32* ar,
                                          const unsigned Bh[8][2][4],
                                          const unsigned Bl[8][2][4],
                                          float c[2][4][4])
{
    #pragma unroll
    for (int ks = 0; ks < 8; ks++) {
        const u32 ko = ks*32;
        unsigned ah[2][4], al[2][4];
        LDSM4(ah[0][0],ah[0][1],ah[0][2],ah[0][3], aB + ar[0] + ko);
        LDSM4(ah[1][0],ah[1][1],ah[1][2],ah[1][3], aB + ar[1] + ko);
        LDSM4(al[0][0],al[0][1],al[0][2],al[0][3], aB + APL64 + ar[0] + ko);
        LDSM4(al[1][0],al[1][1],al[1][2],al[1][3], aB + APL64 + ar[1] + ko);
        #pragma unroll
        for (int mf = 0; mf < 2; mf++)
            #pragma unroll
            for (int g = 0; g < 2; g++) {
                MMA_BF16(c[mf][2*g+0], ah[mf][0],ah[mf][1],ah[mf][2],ah[mf][3],
                         Bh[ks][g][0],Bh[ks][g][2]);
                MMA_BF16(c[mf][2*g+1], ah[mf][0],ah[mf][1],ah[mf][2],ah[mf][3],
                         Bh[ks][g][1],Bh[ks][g][3]);
            }
        #pragma unroll
        for (int mf = 0; mf < 2; mf++)
            #pragma unroll
            for (int g = 0; g < 2; g++) {
                MMA_BF16(c[mf][2*g+0], al[mf][0],al[mf][1],al[mf][2],al[mf][3],
                         Bh[ks][g][0],Bh[ks][g][2]);
                MMA_BF16(c[mf][2*g+1], al[mf][0],al[mf][1],al[mf][2],al[mf][3],
                         Bh[ks][g][1],Bh[ks][g][3]);
            }
        #pragma unroll
        for (int mf = 0; mf < 2; mf++)
            #pragma unroll
            for (int g = 0; g < 2; g++) {
                MMA_BF16(c[mf][2*g+0], ah[mf][0],ah[mf][1],ah[mf][2],ah[mf][3],
                         Bl[ks][g][0],Bl[ks][g][2]);
                MMA_BF16(c[mf][2*g+1], ah[mf][0],ah[mf][1],ah[mf][2],ah[mf][3],
                         Bl[ks][g][1],Bl[ks][g][3]);
            }
    }
}

// ---- 64-row 3-term core, smem B (for second weight matrix) ----
__device__ __forceinline__ void gemm64_sB(u32 aB, u32 bB,
                                          const u32* ar, const u32* br,
                                          float c[2][4][4])
{
    #pragma unroll
    for (int ks = 0; ks < 8; ks++) {
        const u32 ko = ks*32;
        unsigned ah[2][4], al[2][4], bh[2][4], bl[2][4];
        LDSM4(ah[0][0],ah[0][1],ah[0][2],ah[0][3], aB + ar[0] + ko);
        LDSM4(ah[1][0],ah[1][1],ah[1][2],ah[1][3], aB + ar[1] + ko);
        LDSM4(al[0][0],al[0][1],al[0][2],al[0][3], aB + APL64 + ar[0] + ko);
        LDSM4(al[1][0],al[1][1],al[1][2],al[1][3], aB + APL64 + ar[1] + ko);
        LDSM4(bh[0][0],bh[0][1],bh[0][2],bh[0][3], bB + br[0] + ko);
        LDSM4(bh[1][0],bh[1][1],bh[1][2],bh[1][3], bB + br[1] + ko);
        #pragma unroll
        for (int mf = 0; mf < 2; mf++)
            #pragma unroll
            for (int g = 0; g < 2; g++) {
                MMA_BF16(c[mf][2*g+0], ah[mf][0],ah[mf][1],ah[mf][2],ah[mf][3],
                         bh[g][0],bh[g][2]);
                MMA_BF16(c[mf][2*g+1], ah[mf][0],ah[mf][1],ah[mf][2],ah[mf][3],
                         bh[g][1],bh[g][3]);
            }
        LDSM4(bl[0][0],bl[0][1],bl[0][2],bl[0][3], bB + PL + br[0] + ko);
        LDSM4(bl[1][0],bl[1][1],bl[1][2],bl[1][3], bB + PL + br[1] + ko);
        #pragma unroll
        for (int mf = 0; mf < 2; mf++)
            #pragma unroll
            for (int g = 0; g < 2; g++) {
                MMA_BF16(c[mf][2*g+0], al[mf][0],al[mf][1],al[mf][2],al[mf][3],
                         bh[g][0],bh[g][2]);
                MMA_BF16(c[mf][2*g+1], al[mf][0],al[mf][1],al[mf][2],al[mf][3],
                         bh[g][1],bh[g][3]);
            }
        #pragma unroll
        for (int mf = 0; mf < 2; mf++)
            #pragma unroll
            for (int g = 0; g < 2; g++) {
                MMA_BF16(c[mf][2*g+0], ah[mf][0],ah[mf][1],ah[mf][2],ah[mf][3],
                         bl[g][0],bl[g][2]);
                MMA_BF16(c[mf][2*g+1], ah[mf][0],ah[mf][1],ah[mf][2],ah[mf][3],
                         bl[g][1],bl[g][3]);
            }
    }
}

// ---- smem loaders (256 threads; caller commits) ----
__device__ __forceinline__ void loadW(u32 dst, const u16* blob, int tid) {
    #pragma unroll
    for (int it = 0; it < 16; it++) {
        int ch = tid + it*NT;
        int pl = ch >> 11, rem = ch & 2047, r = rem >> 4, q = rem & 15;
        CP16(dst + pl*PL + r*272 + q*16, blob + (size_t)pl*16384 + r*128 + q*8);
    }
}
__device__ __forceinline__ void loadA64(u32 dst, const u16* Ah, const u16* Al,
                                        int rowbase, const int* idx, int tid) {
    #pragma unroll
    for (int it = 0; it < 8; it++) {
        int ch = tid + it*NT;
        int pl = ch >> 10, rem = ch & 1023, r = rem >> 4, q = rem & 15;
        int row = idx ? idx[rowbase + r] : (rowbase + r);
        CP16(dst + pl*APL64 + r*272 + q*16, (pl ? Al : Ah) + (size_t)row*HH + q*8);
    }
}

// ---------------- packing kernels ----------------
__global__ void pack_x_kernel(const float* __restrict__ x) {
    int idx = blockIdx.x*256 + threadIdx.x;
    u16 h, l; splitf(x[idx], h, l);
    g_xph[idx] = h; g_xpl[idx] = l;
}
__global__ void fold_M_kernel(const float* __restrict__ npw, const float* __restrict__ ipw) {
    int k = blockIdx.x, n = threadIdx.x;
    float s = 0.f;
    for (int c = 0; c < HH; c++) s += npw[k*HH + c] * ipw[c*HH + n];
    u16 h, l; splitf(s, h, l);
    g_Mb[n*128 + k] = h; g_Mb[16384 + n*128 + k] = l;
}
__global__ void fold_vec_kernel(const float* __restrict__ lpw, const float* __restrict__ npb,
                                const float* __restrict__ lpb, const float* __restrict__ remb,
                                const float* __restrict__ ipw, const float* __restrict__ ipb) {
    int j = threadIdx.x;
    float v = 0.f, b = ipb[j], r0 = 0.f, r1 = 0.f;
    for (int k = 0; k < HH; k++) {
        float wa = ipw[k*HH + j];
        float wb = ipw[(HH + k)*HH + j];
        float wc = ipw[(2*HH + k)*HH + j];
        v  += lpw[k] * wb;
        b  += npb[k] * wa + lpb[k] * wb;
        r0 += remb[k] * wc;
        r1 += remb[HH + k] * wc;
    }
    g_vlogp[j] = v; g_bias0[j] = b; g_root[j] = r0; g_root[HH + j] = r1;
}
__global__ void pack_w12(const float* __restrict__ W1, const float* __restrict__ W2) {
    int l = blockIdx.y;
    int idx = blockIdx.x*256 + threadIdx.x;
    int k = idx >> 7, n = idx & 127;
    const float* W = blockIdx.z ? W2 : W1;
    u16* out = blockIdx.z ? g_w2b : g_w1b;
    u16 h, lo; splitf(W[(size_t)l*16384 + idx], h, lo);
    out[(size_t)l*32768 + n*128 + k] = h;
    out[(size_t)l*32768 + 16384 + n*128 + k] = lo;
}
__global__ void pack_w256(const float* __restrict__ W, u16* __restrict__ out) {
    int l = blockIdx.y;
    int idx = blockIdx.x*256 + threadIdx.x;
    int kg = idx >> 7, n = idx & 127;
    int half = kg >> 7, kl = kg & 127;
    u16 h, lo; splitf(W[(size_t)l*32768 + idx], h, lo);
    out[(size_t)l*65536 + half*32768 + n*128 + kl] = h;
    out[(size_t)l*65536 + half*32768 + 16384 + n*128 + kl] = lo;
}

// ---------------- counts / CSR build ----------------
__global__ void zero_all_kernel() {
    int i = blockIdx.x*blockDim.x + threadIdx.x;
    g_xagg[i] = 0.f;
    if (i < NN) g_cnt[i] = 0;
    if (i < 2*HH) g_stats[i] = 0.f;
}
__global__ void count_kernel(const int* __restrict__ nodes) {
    int i = blockIdx.x*blockDim.x + threadIdx.x;
    if (i < MROWS) atomicAdd(&g_cnt[nodes[i]], 1);
}
__global__ void inv_kernel() {
    int i = blockIdx.x*blockDim.x + threadIdx.x;
    if (i < NN) g_inv[i] = 1.f / (float)max(g_cnt[i], 1);
}
__global__ void pack_xagg_kernel() {
    int idx = blockIdx.x*256 + threadIdx.x;
    int row = idx >> 7;
    float v = g_xagg[idx] * g_inv[row];
    u16 h, l; splitf(v, h, l);
    g_xah[idx] = h; g_xal[idx] = l;
    g_xagg[idx] = 0.f;
    if (blockIdx.x == 0 && threadIdx.x < 2*HH) g_stats[threadIdx.x] = 0.f;
}
__global__ void build_csr_kernel(const int* __restrict__ esrc, const int* __restrict__ edst,
                                 const int* __restrict__ eptr) {
    __shared__ int cnt[KK+1];
    __shared__ int pos[KK];
    const int s = blockIdx.x, tid = threadIdx.x;
    const int e0 = eptr[s], e1 = eptr[s+1];
    if (tid <= KK) cnt[tid] = 0;
    __syncthreads();
    for (int i = e0 + tid; i < e1; i += 128) atomicAdd(&cnt[edst[i] + 1], 1);
    __syncthreads();
    if (tid == 0)
        for (int r = 1; r <= KK; r++) cnt[r] += cnt[r-1];
    __syncthreads();
    if (tid < KK) pos[tid] = cnt[tid];
    if (tid <= KK) g_rowptr[s*(KK+1) + tid] = cnt[tid];
    __syncthreads();
    for (int i = e0 + tid; i < e1; i += 128) {
        int p = atomicAdd(&pos[edst[i]], 1);
        g_esrt[e0 + p] = esrc[i];
    }
}

// ---------------- persistent init GEMM (64-row tiles, 8 warps, reg-B) ----------------
__global__ void __launch_bounds__(NT, 1)
init_gemm(const float* __restrict__ logp, const int* __restrict__ rootl,
          const int* __restrict__ nodes, float* __restrict__ Cout)
{
    extern __shared__ __align__(16) char sm[];
    const u32 sb = smem_u32(sm);          // M planes [0,2PL); A slots 2PL + s*PL (3 slots)
    const int tid = threadIdx.x, lane = tid & 31, warp = tid >> 5;
    const int wm = warp & 1, wn = warp >> 1;

    loadW(sb, g_Mb, tid);
    loadA64(sb + 2*PL, g_xph, g_xpl, blockIdx.x * 64, nodes, tid);
    CPCOMMIT();

    u32 ar[2], br[2];
    frag_a(lane, wm, ar);
    frag_b(lane, wn, br);
    const int gid = lane >> 2, tig = lane & 3;

    CPWAIT(0); __syncthreads();
    unsigned Bh[8][2][4], Bl[8][2][4];
    PRELOADB(Bh, Bl, sb, br);

    int j = 0;
    for (int t = blockIdx.x; t < MROWS/64; t += NSM, j++) {
        int tn = t + NSM;
        if (tn < MROWS/64) {
            int sn = (j+1) % 3;
            loadA64(sb + 2*PL + sn*PL, g_xph, g_xpl, tn*64, nodes, tid);
            CPCOMMIT();
            CPWAIT(1);
        } else {
            CPWAIT(0);
        }
        __syncthreads();

        float c[2][4][4]; ZERO_C24(c);
        gemm64_rB(sb + 2*PL + (j%3)*PL, ar, Bh, Bl, c);

        int brow = t * 64;
        #pragma unroll
        for (int mf = 0; mf < 2; mf++) {
            #pragma unroll
            for (int half = 0; half < 2; half++) {
                int gr = brow + wm*32 + mf*16 + half*8 + gid;
                int sub = gr >> 6;
                float lp = logp[sub];
                int isr = ((gr & 63) == rootl[sub]) ? 1 : 0;
                #pragma unroll
                for (int nf = 0; nf < 4; nf++) {
                    int n0 = wn*32 + nf*8 + tig*2;
                    float v0 = c[mf][nf][half*2+0] + g_bias0[n0]
                             + lp * g_vlogp[n0]   + g_root[isr*HH + n0];
                    float v1 = c[mf][nf][half*2+1] + g_bias0[n0+1]
                             + lp * g_vlogp[n0+1] + g_root[isr*HH + n0+1];
                    float2 o; o.x = v0; o.y = v1;
                    *(float2*)(Cout + (size_t)gr*HH + n0) = o;
                }
            }
        }
        // 3-slot A buffer: no trailing sync needed
    }
}

// ---------------- persistent fused layer kernel (W1 reg-B, W2 smem) ----------------
__global__ void __launch_bounds__(NT, 1)
layer12_kernel(const u16* __restrict__ w1b, const u16* __restrict__ w2b,
               const float* __restrict__ b1, const float* __restrict__ b2,
               const int* __restrict__ aidx)
{
    extern __shared__ __align__(16) char sm[];
    const u32 sb = smem_u32(sm);          // W1 [0,2PL); W2 [2PL,4PL); A slots 4PL + s*PL
    const int tid = threadIdx.x, lane = tid & 31, warp = tid >> 5;
    const int wm = warp & 1, wn = warp >> 1;
    const int barid = 1 + wm;

    loadW(sb, w1b, tid);
    loadW(sb + 2*PL, w2b, tid);
    loadA64(sb + 4*PL, g_zph, g_zpl, blockIdx.x * 64, nullptr, tid);
    CPCOMMIT();

    u32 ar[2], br[2];
    frag_a(lane, wm, ar);
    frag_b(lane, wn, br);
    const int gid = lane >> 2, tig = lane & 3;

    CPWAIT(0); __syncthreads();
    unsigned Bh[8][2][4], Bl[8][2][4];
    PRELOADB(Bh, Bl, sb, br);             // W1 resident in registers

    int j = 0;
    for (int t = blockIdx.x; t < MROWS/64; t += NSM, j++) {
        int tn = t + NSM;
        if (tn < MROWS/64) {
            loadA64(sb + 4*PL + ((j+1)&1)*PL, g_zph, g_zpl, tn*64, nullptr, tid);
            CPCOMMIT();
            CPWAIT(1);
        } else {
            CPWAIT(0);
        }
        __syncthreads();

        const u32 aslot = sb + 4*PL + (j&1)*PL;
        float c[2][4][4]; ZERO_C24(c);
        gemm64_rB(aslot, ar, Bh, Bl, c);    // z @ W1 (reg B)
        BARG(barid);

        char* aptr = sm + (4*PL + (j&1)*PL);
        #pragma unroll
        for (int mf = 0; mf < 2; mf++) {
            #pragma unroll
            for (int half = 0; half < 2; half++) {
                int m = wm*32 + mf*16 + half*8 + gid;
                #pragma unroll
                for (int nf = 0; nf < 4; nf++) {
                    int n0 = wn*32 + nf*8 + tig*2;
                    float v0 = fmaxf(c[mf][nf][half*2+0] + b1[n0],   0.f);
                    float v1 = fmaxf(c[mf][nf][half*2+1] + b1[n0+1], 0.f);
                    u32 hi, lo; pack2(v0, v1, hi, lo);
                    u32 off = m*272 + n0*2;
                    *(u32*)(aptr + off)         = hi;
                    *(u32*)(aptr + APL64 + off) = lo;
                }
            }
        }
        BARG(barid);

        ZERO_C24(c);
        gemm64_sB(aslot, sb + 2*PL, ar, br, c);   // t @ W2 (smem B)

        int brow = t * 64;
        #pragma unroll
        for (int mf = 0; mf < 2; mf++) {
            #pragma unroll
            for (int half = 0; half < 2; half++) {
                int gr = brow + wm*32 + mf*16 + half*8 + gid;
                int nd = aidx[gr];
                #pragma unroll
                for (int nf = 0; nf < 4; nf++) {
                    int n0 = wn*32 + nf*8 + tig*2;
                    float v0 = c[mf][nf][half*2+0] + b2[n0];
                    float v1 = c[mf][nf][half*2+1] + b2[n0+1];
                    u32 hi, lo; pack2(v0, v1, hi, lo);
                    *(u32*)(g_z2h + (size_t)gr*HH + n0) = hi;
                    *(u32*)(g_z2l + (size_t)gr*HH + n0) = lo;
                    atomicAdd(&g_xagg[(size_t)nd*HH + n0],     v0);
                    atomicAdd(&g_xagg[(size_t)nd*HH + n0 + 1], v1);
                }
            }
        }
        __syncthreads();
    }
}

// ---------------- persistent mp2 kernel (Wh0 reg-B, Wh1 smem) ----------------
__global__ void __launch_bounds__(NT, 1)
mp2_kernel(const u16* __restrict__ blob, const float* __restrict__ bias,
           const int* __restrict__ aidx, float* __restrict__ uout)
{
    extern __shared__ __align__(16) char sm[];
    const u32 sb = smem_u32(sm);          // Wh0 [0,2PL); Wh1 [2PL,4PL); slotZ 4PL; slotX 5PL
    const int tid = threadIdx.x, lane = tid & 31, warp = tid >> 5;
    const int wm = warp & 1, wn = warp >> 1;

    loadW(sb, blob, tid);
    loadW(sb + 2*PL, blob + 32768, tid);
    loadA64(sb + 4*PL, g_z2h, g_z2l, blockIdx.x * 64, nullptr, tid);
    CPCOMMIT();

    u32 ar[2], br[2];
    frag_a(lane, wm, ar);
    frag_b(lane, wn, br);
    const int gid = lane >> 2, tig = lane & 3;

    CPWAIT(0); __syncthreads();
    unsigned Bh[8][2][4], Bl[8][2][4];
    PRELOADB(Bh, Bl, sb, br);             // Wh0 resident in registers

    float s0[4], s1[4], q0[4], q1[4];
    #pragma unroll
    for (int nf = 0; nf < 4; nf++) { s0[nf]=0.f; s1[nf]=0.f; q0[nf]=0.f; q1[nf]=0.f; }

    for (int t = blockIdx.x; t < MROWS/64; t += NSM) {
        loadA64(sb + 5*PL, g_xah, g_xal, t*64, aidx, tid);
        CPCOMMIT();
        CPWAIT(1);                       // z2 chunk ready
        __syncthreads();

        float c[2][4][4]; ZERO_C24(c);
        gemm64_rB(sb + 4*PL, ar, Bh, Bl, c);        // z2 @ Wh0 (reg B)
        __syncthreads();                             // slotZ reads done

        int tn = t + NSM;
        if (tn < MROWS/64) {
            loadA64(sb + 4*PL, g_z2h, g_z2l, tn*64, nullptr, tid);
            CPCOMMIT();
            CPWAIT(1);                  // xa chunk ready
        } else {
            CPWAIT(0);
        }
        __syncthreads();

        gemm64_sB(sb + 5*PL, sb + 2*PL, ar, br, c); // += xa @ Wh1 (smem B)

        int brow = t * 64;
        #pragma unroll
        for (int mf = 0; mf < 2; mf++) {
            #pragma unroll
            for (int half = 0; half < 2; half++) {
                int gr = brow + wm*32 + mf*16 + half*8 + gid;
                #pragma unroll
                for (int nf = 0; nf < 4; nf++) {
                    int n0 = wn*32 + nf*8 + tig*2;
                    float v0 = fmaxf(c[mf][nf][half*2+0] + bias[n0],   0.f);
                    float v1 = fmaxf(c[mf][nf][half*2+1] + bias[n0+1], 0.f);
                    float2 o; o.x = v0; o.y = v1;
                    *(float2*)(uout + (size_t)gr*HH + n0) = o;
                    s0[nf] += v0; s1[nf] += v1;
                    q0[nf] += v0*v0; q1[nf] += v1*v1;
                }
            }
        }
        __syncthreads();
    }

    #pragma unroll
    for (int nf = 0; nf < 4; nf++) {
        #pragma unroll
        for (int off = 4; off < 32; off <<= 1) {
            s0[nf] += __shfl_xor_sync(0xFFFFFFFFu, s0[nf], off);
            s1[nf] += __shfl_xor_sync(0xFFFFFFFFu, s1[nf], off);
            q0[nf] += __shfl_xor_sync(0xFFFFFFFFu, q0[nf], off);
            q1[nf] += __shfl_xor_sync(0xFFFFFFFFu, q1[nf], off);
        }
    }
    if (gid == 0) {
        #pragma unroll
        for (int nf = 0; nf < 4; nf++) {
            int n0 = wn*32 + nf*8 + tig*2;
            atomicAdd(&g_stats[n0],      s0[nf]);
            atomicAdd(&g_stats[n0+1],    s1[nf]);
            atomicAdd(&g_stats[HH+n0],   q0[nf]);
            atomicAdd(&g_stats[HH+n0+1], q1[nf]);
        }
    }
}

// ---------------- agg via CSR: register accumulation per row ----------------
template<int FUSE_BN>
__global__ void __launch_bounds__(256)
agg_kernel(const float* __restrict__ u, float* __restrict__ H,
           u16* __restrict__ zph, u16* __restrict__ zpl,
           const int* __restrict__ eptr, const float* __restrict__ geps,
           const float* __restrict__ gamma, const float* __restrict__ beta,
           int l)
{
    extern __shared__ float fsm[];
    float* hsm = fsm;                       // [KK][HH] = 32KB
    __shared__ int ssrc[1024];
    __shared__ int rp[KK+1];
    const int s = blockIdx.x;
    const int tid = threadIdx.x;
    const int grp = tid >> 7, col = tid & 127;
    const float eps1 = 1.f + geps[l];
    const size_t base = (size_t)s * KK;

    float g = 0.f, bt = 0.f, mu = 0.f;
    if (FUSE_BN) {
        const float invM = 1.f / (float)MROWS;
        mu = g_stats[col] * invM;
        float var = g_stats[HH + col] * invM - mu*mu;
        g = gamma[col] * rsqrtf(var + 1e-5f);
        bt = beta[col];
    }

    #pragma unroll 4
    for (int r = grp*32; r < grp*32 + 32; r++) {
        float hv;
        if (FUSE_BN) {
            float uv = u[(base + r)*HH + col];
            hv = (uv - mu) * g + bt + H[(base + r)*HH + col];
            H[(base + r)*HH + col] = hv;
        } else {
            hv = H[(base + r)*HH + col];
        }
        hsm[r*HH + col] = hv;
    }
    const int e0 = eptr[s], e1 = eptr[s+1];
    const int etot = e1 - e0;
    for (int i = tid; i < etot && i < 1024; i += 256) ssrc[i] = g_esrt[e0 + i];
    if (tid <= KK) rp[tid] = g_rowptr[s*(KK+1) + tid];
    __syncthreads();

    const bool cached = (etot <= 1024);
    for (int r = grp*32; r < grp*32 + 32; r++) {
        float acc = eps1 * hsm[r*HH + col];
        int a = rp[r], b = rp[r+1];
        if (cached) {
            for (int i = a; i < b; i++)
                acc += hsm[ssrc[i]*HH + col];
        } else {
            for (int i = a; i < b; i++)
                acc += hsm[g_esrt[e0 + i]*HH + col];
        }
        u16 h, lo; splitf(acc, h, lo);
        zph[(base + r)*HH + col] = h;
        zpl[(base + r)*HH + col] = lo;
    }
}

// ---------------- final batchnorm apply ----------------
__global__ void bn_apply_kernel(const float* __restrict__ u, float* __restrict__ h,
                                const float* __restrict__ gamma, const float* __restrict__ beta) {
    int idx = blockIdx.x*blockDim.x + threadIdx.x;
    int c = idx & 127;
    const float invM = 1.f / (float)MROWS;
    float mu  = g_stats[c] * invM;
    float var = g_stats[HH + c] * invM - mu*mu;
    float g = gamma[c] * rsqrtf(var + 1e-5f);
    h[idx] = (u[idx] - mu) * g + beta[c] + h[idx];
}

// ---------------- launch ----------------
extern "C" void kernel_launch(void* const* d_in, const int* in_sizes, int n_in,
                              void* d_out, int out_size) {
    const float* x    = (const float*)d_in[0];
    const float* logp = (const float*)d_in[1];
    const float* npw  = (const float*)d_in[2];
    const float* npb  = (const float*)d_in[3];
    const float* lpw  = (const float*)d_in[4];
    const float* lpb  = (const float*)d_in[5];
    const float* remb = (const float*)d_in[6];
    const float* ipw  = (const float*)d_in[7];
    const float* ipb  = (const float*)d_in[8];
    const float* geps = (const float*)d_in[9];
    const float* w1   = (const float*)d_in[10];
    const float* b1   = (const float*)d_in[11];
    const float* w2   = (const float*)d_in[12];
    const float* b2   = (const float*)d_in[13];
    const float* mp2w = (const float*)d_in[14];
    const float* mp2b = (const float*)d_in[15];
    const float* bng  = (const float*)d_in[16];
    const float* bnb  = (const float*)d_in[17];
    const int* nodes  = (const int*)d_in[18];
    const int* rootl  = (const int*)d_in[19];
    const int* eidx   = (const int*)d_in[20];
    const int* eptr   = (const int*)d_in[21];
    float* hout = (float*)d_out;

    float *p_u;
    u16 *p_zph, *p_zpl, *p_w1b, *p_w2b, *p_mp2b;
    cudaGetSymbolAddress((void**)&p_u, g_u);
    cudaGetSymbolAddress((void**)&p_zph, g_zph);
    cudaGetSymbolAddress((void**)&p_zpl, g_zpl);
    cudaGetSymbolAddress((void**)&p_w1b, g_w1b);
    cudaGetSymbolAddress((void**)&p_w2b, g_w2b);
    cudaGetSymbolAddress((void**)&p_mp2b, g_mp2b);

    const int SM_INIT = 5*PL;             // 174080 (3 A slots)
    const int SM_BIG  = 6*PL;             // 208896
    const int SMA = KK*HH*4;              // 32768
    cudaFuncSetAttribute(init_gemm,      cudaFuncAttributeMaxDynamicSharedMemorySize, SM_INIT);
    cudaFuncSetAttribute(layer12_kernel, cudaFuncAttributeMaxDynamicSharedMemorySize, SM_BIG);
    cudaFuncSetAttribute(mp2_kernel,     cudaFuncAttributeMaxDynamicSharedMemorySize, SM_BIG);
    cudaFuncSetAttribute(agg_kernel<0>,  cudaFuncAttributeMaxDynamicSharedMemorySize, SMA);
    cudaFuncSetAttribute(agg_kernel<1>,  cudaFuncAttributeMaxDynamicSharedMemorySize, SMA);

    const int* esrc = eidx;
    const int* edst = eidx + EE;

    // ---- prologue (init_gemm is launch #4 -> captured by ncu) ----
    pack_x_kernel<<<(NN*HH)/256, 256>>>(x);                       // 1
    fold_M_kernel<<<128, 128>>>(npw, ipw);                        // 2
    fold_vec_kernel<<<1, 128>>>(lpw, npb, lpb, remb, ipw, ipb);   // 3
    init_gemm<<<NSM, NT, SM_INIT>>>(logp, rootl, nodes, hout);    // 4 <- profiled
    pack_w12<<<dim3(64, LL, 2), 256>>>(w1, w2);                   // 5
    pack_w256<<<dim3(128, LL), 256>>>(mp2w, p_mp2b);              // 6
    zero_all_kernel<<<(NN*HH)/256, 256>>>();                      // 7
    count_kernel<<<MROWS/256, 256>>>(nodes);                      // 8
    inv_kernel<<<(NN + 255)/256, 256>>>();                        // 9
    build_csr_kernel<<<SS, 128>>>(esrc, edst, eptr);              // 10

    // ---- layers ----
    for (int l = 0; l < LL; l++) {
        if (l == 0)
            agg_kernel<0><<<SS, 256, SMA>>>(nullptr, hout, p_zph, p_zpl,
                                            eptr, geps, nullptr, nullptr, l);
        else
            agg_kernel<1><<<SS, 256, SMA>>>(p_u, hout, p_zph, p_zpl,
                                            eptr, geps, bng + (l-1)*HH, bnb + (l-1)*HH, l);

        layer12_kernel<<<NSM, NT, SM_BIG>>>(p_w1b + (size_t)l*32768,
                                            p_w2b + (size_t)l*32768,
                                            b1 + l*HH, b2 + l*HH, nodes);

        pack_xagg_kernel<<<(NN*HH)/256, 256>>>();

        mp2_kernel<<<NSM, NT, SM_BIG>>>(p_mp2b + (size_t)l*65536,
                                        mp2b + l*HH, nodes, p_u);
    }

    // ---- final BN apply ----
    bn_apply_kernel<<<(MROWS*HH)/256, 256>>>(p_u, hout, bng + (LL-1)*HH, bnb + (LL-1)*HH);
}